// round 7
// baseline (speedup 1.0000x reference)
#include <cuda_runtime.h>
#include <cuda_bf16.h>
#include <math.h>

// Problem constants
#define SQ 256
#define NB 64
#define NH 512
#define OUT_SEQ (SQ*NB*2*NH)   // 16,777,216 floats of [S,B,2H]; hidd follows

// ---------------- device scratch (no allocs allowed) ----------------
// P[d][gate][t][j][b]  : x-side projections + bias  (201 MB)
__device__ float dP[2u*3u*SQ*NH*NB];
// Y0[d][t][j][b]       : layer-0 outputs, transposed for layer-1 proj B-loads
__device__ float dY0T[2u*SQ*NH*NB];
// hT[d][j][b], uT[d][j][b]
__device__ float dHT[2*NH*NB];
__device__ float dUT[2*NH*NB];
__device__ unsigned gBarCnt[2];
__device__ volatile unsigned gBarGen[2];

// Per-direction global barrier over 64 CTAs. Sense-free generation counter.
// __threadfence() (scope gpu >= cluster) emits CCTL.IVALL on sm_103a ->
// L1D invalidated, so post-barrier plain LDGs see other SMs' stores.
__device__ __forceinline__ void gbar(int d) {
    __syncthreads();
    if (threadIdx.x == 0) {
        __threadfence();
        unsigned gen = gBarGen[d];
        unsigned prev = atomicAdd(&gBarCnt[d], 1u);
        if (prev == 63u) {
            gBarCnt[d] = 0u;
            __threadfence();
            gBarGen[d] = gen + 1u;
        } else {
            while (gBarGen[d] == gen) { }
        }
        __threadfence();
    }
    __syncthreads();
}

__device__ __forceinline__ float sigf(float x) { return 1.0f / (1.0f + expf(-x)); }

__device__ __forceinline__ void fma4(float a, const float4& b, float4& c) {
    c.x += a * b.x; c.y += a * b.y; c.z += a * b.z; c.w += a * b.w;
}

// Shared memory union layout (floats):
//  proj phase:   As[16][132] at 0 (2112), Bs[16][68] at 2112 (1088)
//  recur phase:  sWrzT[512][16] at 0 (8192), sWsT[512][8] at 8192 (4096),
//                sZ[8][64] at 12288, sHold[8][64] at 12800, sRed[16384] at 13312
#define SMEM_FLOATS 29696

__global__ void __launch_bounds__(256, 1)
bigru_kernel(const int*   __restrict__ tokens,
             const float* __restrict__ emb,
             const float* __restrict__ Wr,
             const float* __restrict__ Wz,
             const float* __restrict__ Ws,
             const float* __restrict__ br,
             const float* __restrict__ bz,
             const float* __restrict__ bs,
             float*       __restrict__ out)
{
    extern __shared__ float smem[];
    __shared__ int sTok[64];

    const int tid = threadIdx.x;
    const int d   = blockIdx.x >> 6;   // direction 0/1
    const int c   = blockIdx.x & 63;   // cta within direction
    const int J0  = c * 8;             // owned hidden-unit slice

    float* HT = dHT + d * (NH*NB);
    float* UT = dUT + d * (NH*NB);
    float* P  = dP   + (size_t)d * 3u * SQ * NH * NB;
    float* Y0 = dY0T + (size_t)d * SQ * NH * NB;

    float* As    = smem;            // proj
    float* Bs    = smem + 2112;     // proj
    float* sWrzT = smem;            // recur  [k*16 + row], rows 0-7=r, 8-15=z
    float* sWsT  = smem + 8192;     // recur  [k*8 + row]
    float* sZ    = smem + 12288;    // [j*64 + b]
    float* sHold = smem + 12800;    // [j*64 + b]
    float* sRed  = smem + 13312;    // reduction buffer

    for (int l = 0; l < 2; l++) {
        const int wlo = (d*2 + l) * 512;   // weight row block for (dir,layer)

        // zero own h slice (h0 = 0); visible to all after the proj-end gbar
        for (int i = tid; i < 512; i += 256) HT[J0*64 + i] = 0.0f;

        // ---------------- input projections: P[gate][t][j][b] ----------------
        // 3 gates x 4 j-tiles(128) x 256 t = 3072 tiles; 48 per CTA,
        // t innermost so the weight A-tile stays hot in L1/L2.
        for (int tb = 0; tb < 48; tb++) {
            const int tile = c * 48 + tb;
            const int t    = tile & 255;
            const int grp  = tile >> 8;     // 0..11
            const int gate = grp >> 2;
            const int jt   = grp & 3;
            const float* W = (gate == 0) ? Wr : (gate == 1) ? Wz : Ws;
            const float* Wbase = W + (size_t)(wlo + jt*128) * 1024;
            const int ty = tid >> 4, tx = tid & 15;

            if (l == 0 && tid < 64) {
                const int tp = d ? (255 - t) : t;
                sTok[tid] = tokens[tp*64 + tid];
            }

            float4 acc[8];
            #pragma unroll
            for (int r = 0; r < 8; r++) acc[r] = make_float4(0.f,0.f,0.f,0.f);

            for (int kc = 0; kc < 512; kc += 16) {
                __syncthreads();
                // A: weights 128j x 16k -> As[k][j] (transposed)
                #pragma unroll
                for (int u = 0; u < 2; u++) {
                    const int idx = tid*2 + u;          // 0..511
                    const int j = idx >> 2, kq = idx & 3;
                    const float4 v = *(const float4*)(Wbase + (size_t)j*1024 + kc + kq*4);
                    As[(kq*4+0)*132 + j] = v.x;
                    As[(kq*4+1)*132 + j] = v.y;
                    As[(kq*4+2)*132 + j] = v.z;
                    As[(kq*4+3)*132 + j] = v.w;
                }
                // B: inputs 16k x 64b -> Bs[k][b]
                if (l == 0) {
                    const int b = tid >> 2, kq = tid & 3;
                    const float4 v = *(const float4*)(emb + (size_t)sTok[b]*512 + kc + kq*4);
                    Bs[(kq*4+0)*68 + b] = v.x;
                    Bs[(kq*4+1)*68 + b] = v.y;
                    Bs[(kq*4+2)*68 + b] = v.z;
                    Bs[(kq*4+3)*68 + b] = v.w;
                } else {
                    const int k = tid >> 4, b4 = (tid & 15) * 4;
                    *(float4*)(Bs + k*68 + b4) =
                        *(const float4*)(Y0 + ((size_t)t*512 + kc + k)*64 + b4);
                }
                __syncthreads();
                #pragma unroll
                for (int k = 0; k < 16; k++) {
                    const float4 a0 = *(const float4*)(As + k*132 + ty*8);
                    const float4 a1 = *(const float4*)(As + k*132 + ty*8 + 4);
                    const float4 bq = *(const float4*)(Bs + k*68 + tx*4);
                    const float ar[8] = {a0.x,a0.y,a0.z,a0.w,a1.x,a1.y,a1.z,a1.w};
                    #pragma unroll
                    for (int r = 0; r < 8; r++) fma4(ar[r], bq, acc[r]);
                }
            }
            // epilogue: add bias, store P[t][j][b] (b-contiguous, coalesced)
            const float* bias = ((gate==0) ? br : (gate==1) ? bz : bs) + wlo + jt*128 + ty*8;
            float* Pout = P + (((size_t)gate*256 + t)*512 + jt*128 + ty*8)*64 + tx*4;
            #pragma unroll
            for (int r = 0; r < 8; r++) {
                const float bb = bias[r];
                float4 o = acc[r];
                o.x += bb; o.y += bb; o.z += bb; o.w += bb;
                *(float4*)(Pout + (size_t)r*64) = o;
            }
        }
        __syncthreads();

        // ---------------- load recurrence weights into smem ----------------
        for (int idx = tid; idx < 8192; idx += 256) {           // sWrzT[k*16+row]
            const int k = idx >> 4, row = idx & 15;
            const float* W = (row < 8) ? Wr : Wz;
            sWrzT[idx] = W[(size_t)(wlo + J0 + (row & 7))*1024 + 512 + k];
        }
        for (int idx = tid; idx < 4096; idx += 256) {           // sWsT[k*8+row]
            const int k = idx >> 3, row = idx & 7;
            sWsT[idx] = Ws[(size_t)(wlo + J0 + row)*1024 + 512 + k];
        }
        gbar(d);   // proj done, h zeros + P visible everywhere

        // ---------------- recurrence over time ----------------
        for (int t = 0; t < 256; t++) {
            // ---- rz GEMV: 16 rows (r:0-7, z:8-15) x 64 b, K=512 split 16x32 ----
            {
                const int ks = tid >> 4, pos = tid & 15;
                const int rg = pos >> 2, bg = pos & 3;
                float4 acc[4][4];
                #pragma unroll
                for (int r = 0; r < 4; r++)
                    #pragma unroll
                    for (int q = 0; q < 4; q++) acc[r][q] = make_float4(0.f,0.f,0.f,0.f);
                const int k0 = ks * 32;
                for (int k = k0; k < k0 + 32; k++) {
                    const float4 w = *(const float4*)(sWrzT + k*16 + rg*4);
                    const float wr[4] = {w.x, w.y, w.z, w.w};
                    float4 hv[4];
                    #pragma unroll
                    for (int q = 0; q < 4; q++)
                        hv[q] = *(const float4*)(HT + k*64 + bg*16 + q*4);
                    #pragma unroll
                    for (int r = 0; r < 4; r++)
                        #pragma unroll
                        for (int q = 0; q < 4; q++) fma4(wr[r], hv[q], acc[r][q]);
                }
                float* pr = sRed + (ks*16 + rg*4)*64 + bg*16;
                #pragma unroll
                for (int r = 0; r < 4; r++)
                    #pragma unroll
                    for (int q = 0; q < 4; q++)
                        *(float4*)(pr + r*64 + q*4) = acc[r][q];
            }
            __syncthreads();
            // ---- rz reduce + sigmoid; u = r*h to global, z & h_old to smem ----
            {
                const int row = tid >> 4;            // 0..15
                const int b4  = (tid & 15) * 4;
                float4 s = make_float4(0.f,0.f,0.f,0.f);
                #pragma unroll
                for (int ks = 0; ks < 16; ks++) {
                    const float4 v = *(const float4*)(sRed + (ks*16 + row)*64 + b4);
                    s.x += v.x; s.y += v.y; s.z += v.z; s.w += v.w;
                }
                const int gate = row >> 3, j = row & 7;
                const float4 pre = *(const float4*)(P + (((size_t)gate*256 + t)*512 + J0 + j)*64 + b4);
                float4 g;
                g.x = sigf(pre.x + s.x); g.y = sigf(pre.y + s.y);
                g.z = sigf(pre.z + s.z); g.w = sigf(pre.w + s.w);
                if (gate == 0) {
                    const float4 h = *(const float4*)(HT + (J0 + j)*64 + b4);
                    *(float4*)(sHold + j*64 + b4) = h;
                    float4 u;
                    u.x = g.x*h.x; u.y = g.y*h.y; u.z = g.z*h.z; u.w = g.w*h.w;
                    *(float4*)(UT + (J0 + j)*64 + b4) = u;
                } else {
                    *(float4*)(sZ + j*64 + b4) = g;
                }
            }
            gbar(d);   // u visible to all CTAs
            // ---- s GEMV: 8 rows x 64 b, K=512 split 32x16 ----
            {
                const int ks = tid >> 3, pos = tid & 7;
                const int rg = pos >> 2, bg = pos & 3;
                float4 acc[4][4];
                #pragma unroll
                for (int r = 0; r < 4; r++)
                    #pragma unroll
                    for (int q = 0; q < 4; q++) acc[r][q] = make_float4(0.f,0.f,0.f,0.f);
                const int k0 = ks * 16;
                for (int k = k0; k < k0 + 16; k++) {
                    const float4 w = *(const float4*)(sWsT + k*8 + rg*4);
                    const float wr[4] = {w.x, w.y, w.z, w.w};
                    float4 uv[4];
                    #pragma unroll
                    for (int q = 0; q < 4; q++)
                        uv[q] = *(const float4*)(UT + k*64 + bg*16 + q*4);
                    #pragma unroll
                    for (int r = 0; r < 4; r++)
                        #pragma unroll
                        for (int q = 0; q < 4; q++) fma4(wr[r], uv[q], acc[r][q]);
                }
                float* pr = sRed + (ks*8 + rg*4)*64 + bg*16;
                #pragma unroll
                for (int r = 0; r < 4; r++)
                    #pragma unroll
                    for (int q = 0; q < 4; q++)
                        *(float4*)(pr + r*64 + q*4) = acc[r][q];
            }
            __syncthreads();
            // ---- s reduce + tanh + h update + outputs ----
            {
                const int row = tid >> 5;            // 0..7
                const int b2  = (tid & 31) * 2;
                float sx = 0.f, sy = 0.f;
                #pragma unroll
                for (int ks = 0; ks < 32; ks++) {
                    const float2 v = *(const float2*)(sRed + (ks*8 + row)*64 + b2);
                    sx += v.x; sy += v.y;
                }
                const float2 pre = *(const float2*)(P + (((size_t)2*256 + t)*512 + J0 + row)*64 + b2);
                const float ssx = tanhf(pre.x + sx);
                const float ssy = tanhf(pre.y + sy);
                const float2 z = *(const float2*)(sZ    + row*64 + b2);
                const float2 h = *(const float2*)(sHold + row*64 + b2);
                const float hnx = z.x*h.x + (1.f - z.x)*ssx;
                const float hny = z.y*h.y + (1.f - z.y)*ssy;
                *(float2*)(HT + (J0 + row)*64 + b2) = make_float2(hnx, hny);
                if (l == 0) {
                    *(float2*)(Y0 + ((size_t)t*512 + J0 + row)*64 + b2) = make_float2(hnx, hny);
                } else {
                    out[((size_t)t*64 + b2    )*1024 + d*512 + J0 + row] = hnx;
                    out[((size_t)t*64 + b2 + 1)*1024 + d*512 + J0 + row] = hny;
                }
                if (t == 255) {   // final hidden states -> hidd[d*2+l][b][j]
                    out[(size_t)OUT_SEQ + ((size_t)((d*2+l)*64) + b2    )*512 + J0 + row] = hnx;
                    out[(size_t)OUT_SEQ + ((size_t)((d*2+l)*64) + b2 + 1)*512 + J0 + row] = hny;
                }
            }
            gbar(d);   // h (and Y0) visible for next step / next layer
        }
    }
}

extern "C" void kernel_launch(void* const* d_in, const int* in_sizes, int n_in,
                              void* d_out, int out_size) {
    const int*   tokens = (const int*)  d_in[0];
    const float* emb    = (const float*)d_in[1];
    const float* Wr     = (const float*)d_in[2];
    const float* Wz     = (const float*)d_in[3];
    const float* Ws     = (const float*)d_in[4];
    const float* br     = (const float*)d_in[5];
    const float* bz     = (const float*)d_in[6];
    const float* bs     = (const float*)d_in[7];
    float* out = (float*)d_out;

    cudaFuncSetAttribute(bigru_kernel,
                         cudaFuncAttributeMaxDynamicSharedMemorySize,
                         SMEM_FLOATS * sizeof(float));
    bigru_kernel<<<128, 256, SMEM_FLOATS * sizeof(float)>>>(
        tokens, emb, Wr, Wz, Ws, br, bz, bs, out);
}

// round 9
// speedup vs baseline: 1.5132x; 1.5132x over previous
#include <cuda_runtime.h>
#include <math.h>

#define SQ 256
#define NB 64
#define NH 512
#define OUT_SEQ (SQ*NB*2*NH)   // 16,777,216 floats of [S,B,2H]; hidd follows

// ---------------- device scratch (no allocs allowed) ----------------
// P[d][gate][t][j][b] : layer-0 x-side projections + bias (201 MB)
__device__ float dP[2u*3u*SQ*NH*NB];
__device__ float dHT0[2][2][NH*NB];   // layer-0 h, double buffered [dir][buf][j*64+b]
__device__ float dHT1[2][NH*NB];      // layer-1 h
__device__ float dUT0[2][NH*NB];      // layer-0 u = r*h
__device__ float dUT1[2][NH*NB];      // layer-1 u
__device__ unsigned gBarCnt[2];
__device__ volatile unsigned gBarGen[2];

// Per-direction global barrier over 64 CTAs (sense-free generation counter).
// __threadfence() emits CCTL.IVALL on sm_103a -> post-barrier LDGs see other
// SMs' stores.
__device__ __forceinline__ void gbar(int d) {
    __syncthreads();
    if (threadIdx.x == 0) {
        __threadfence();
        unsigned gen = gBarGen[d];
        unsigned prev = atomicAdd(&gBarCnt[d], 1u);
        if (prev == 63u) {
            gBarCnt[d] = 0u;
            __threadfence();
            gBarGen[d] = gen + 1u;
        } else {
            while (gBarGen[d] == gen) { }
        }
        __threadfence();
    }
    __syncthreads();
}

__device__ __forceinline__ float sigf(float x) { return 1.0f / (1.0f + expf(-x)); }

__device__ __forceinline__ void fma4(float a, const float4& b, float4& c) {
    c.x += a * b.x; c.y += a * b.y; c.z += a * b.z; c.w += a * b.w;
}

// ---------------- shared memory layout (floats) ----------------
//  proj phase overlay: As[16][132] at 0 (2112), Bs[16][68] at 2112 (1088)
//  sRed stride 68: 68*4=272 bytes, 272 % 16 == 0 -> float4-aligned every row,
//  and 68 % 32 != 0 -> rows land on shifted banks (no smem conflicts).
#define RSTR 68
#define OFF_WRZ0 0        // [k*16+row], k<512, rows 0-7=r 8-15=z (h-part)   8192
#define OFF_WS0  8192     // [k*8+row],  k<512                              4096
#define OFF_WRZ1 12288    // [k*16+row], k<1024 (x-part then h-part)       16384
#define OFF_WS1  28672    // [k*8+row],  k<1024                             8192
#define OFF_RED  36864    // K-split reduction buffer: 128 rows x 68        8704
#define OFF_Z0   45568
#define OFF_H0   46080
#define OFF_Z1   46592
#define OFF_H1   47104
#define SMEM_FLOATS 47616

// 16-row GEMV, 8 K-splits x KPS each. Wt: [k*16+row] smem. X chosen per split:
// k0 < 512 -> Xlo (indexed by k), else Xhi (pre-offset so X + k*64 is valid).
template<int KPS>
__device__ __forceinline__ void gemv16(const float* __restrict__ Wt,
                                       const float* __restrict__ Xlo,
                                       const float* __restrict__ Xhi,
                                       float* __restrict__ sRed, int tid)
{
    const int split = tid >> 5;
    const int rg = (tid >> 3) & 3;     // rows rg*4 .. rg*4+3
    const int bg = tid & 7;            // b = bg*8 .. bg*8+7
    const int k0 = split * KPS;
    const float* X = (k0 < 512) ? Xlo : Xhi;
    float4 a[4][2];
    #pragma unroll
    for (int r = 0; r < 4; r++) { a[r][0] = make_float4(0.f,0.f,0.f,0.f);
                                  a[r][1] = make_float4(0.f,0.f,0.f,0.f); }
    #pragma unroll 4
    for (int k = k0; k < k0 + KPS; k++) {
        const float4 w  = *(const float4*)(Wt + k*16 + rg*4);
        const float4 x0 = *(const float4*)(X + k*64 + bg*8);
        const float4 x1 = *(const float4*)(X + k*64 + bg*8 + 4);
        fma4(w.x, x0, a[0][0]); fma4(w.x, x1, a[0][1]);
        fma4(w.y, x0, a[1][0]); fma4(w.y, x1, a[1][1]);
        fma4(w.z, x0, a[2][0]); fma4(w.z, x1, a[2][1]);
        fma4(w.w, x0, a[3][0]); fma4(w.w, x1, a[3][1]);
    }
    #pragma unroll
    for (int r = 0; r < 4; r++) {
        *(float4*)(sRed + (split*16 + rg*4 + r)*RSTR + bg*8)     = a[r][0];
        *(float4*)(sRed + (split*16 + rg*4 + r)*RSTR + bg*8 + 4) = a[r][1];
    }
}

// 8-row GEMV, 16 K-splits x KPS each.
template<int KPS>
__device__ __forceinline__ void gemv8(const float* __restrict__ Wt,
                                      const float* __restrict__ Xlo,
                                      const float* __restrict__ Xhi,
                                      float* __restrict__ sRed, int tid)
{
    const int split = tid >> 4;
    const int rg = (tid >> 3) & 1;     // rows rg*4 .. rg*4+3
    const int bg = tid & 7;
    const int k0 = split * KPS;
    const float* X = (k0 < 512) ? Xlo : Xhi;
    float4 a[4][2];
    #pragma unroll
    for (int r = 0; r < 4; r++) { a[r][0] = make_float4(0.f,0.f,0.f,0.f);
                                  a[r][1] = make_float4(0.f,0.f,0.f,0.f); }
    #pragma unroll 4
    for (int k = k0; k < k0 + KPS; k++) {
        const float4 w  = *(const float4*)(Wt + k*8 + rg*4);
        const float4 x0 = *(const float4*)(X + k*64 + bg*8);
        const float4 x1 = *(const float4*)(X + k*64 + bg*8 + 4);
        fma4(w.x, x0, a[0][0]); fma4(w.x, x1, a[0][1]);
        fma4(w.y, x0, a[1][0]); fma4(w.y, x1, a[1][1]);
        fma4(w.z, x0, a[2][0]); fma4(w.z, x1, a[2][1]);
        fma4(w.w, x0, a[3][0]); fma4(w.w, x1, a[3][1]);
    }
    #pragma unroll
    for (int r = 0; r < 4; r++) {
        *(float4*)(sRed + (split*8 + rg*4 + r)*RSTR + bg*8)     = a[r][0];
        *(float4*)(sRed + (split*8 + rg*4 + r)*RSTR + bg*8 + 4) = a[r][1];
    }
}

__global__ void __launch_bounds__(256, 1)
bigru_kernel(const int*   __restrict__ tokens,
             const float* __restrict__ emb,
             const float* __restrict__ Wr,
             const float* __restrict__ Wz,
             const float* __restrict__ Ws,
             const float* __restrict__ br,
             const float* __restrict__ bz,
             const float* __restrict__ bs,
             float*       __restrict__ out)
{
    extern __shared__ float smem[];
    __shared__ int sTok[64];

    const int tid = threadIdx.x;
    const int d   = blockIdx.x >> 6;   // direction 0/1
    const int c   = blockIdx.x & 63;   // cta within direction
    const int J0  = c * 8;             // owned hidden-unit slice (both layers)

    float* P   = dP + (size_t)d * 3u * SQ * NH * NB;
    float* HT1 = dHT1[d];
    float* UT0 = dUT0[d];
    float* UT1 = dUT1[d];

    const int wlo0 = (d*2 + 0) * 512;
    const int wlo1 = (d*2 + 1) * 512;

    float* As   = smem;
    float* Bs   = smem + 2112;
    float* sRed = smem + OFF_RED;
    float* sZ0  = smem + OFF_Z0;
    float* sH0  = smem + OFF_H0;
    float* sZ1  = smem + OFF_Z1;
    float* sH1  = smem + OFF_H1;

    // zero own h slices (h0 = h1 = 0); published by the proj-end gbar
    for (int i = tid; i < 512; i += 256) {
        dHT0[d][0][J0*64 + i] = 0.0f;
        dHT0[d][1][J0*64 + i] = 0.0f;
        HT1[J0*64 + i] = 0.0f;
    }

    // ------------- layer-0 input projections: P[gate][t][j][b] -------------
    // 3 gates x 4 j-tiles(128) x 256 t = 3072 tiles; 48 per CTA.
    for (int tb = 0; tb < 48; tb++) {
        const int tile = c * 48 + tb;
        const int t    = tile & 255;
        const int grp  = tile >> 8;     // 0..11
        const int gate = grp >> 2;
        const int jt   = grp & 3;
        const float* W = (gate == 0) ? Wr : (gate == 1) ? Wz : Ws;
        const float* Wbase = W + (size_t)(wlo0 + jt*128) * 1024;
        const int ty = tid >> 4, tx = tid & 15;

        if (tid < 64) {
            const int tp = d ? (255 - t) : t;
            sTok[tid] = tokens[tp*64 + tid];
        }

        float4 acc[8];
        #pragma unroll
        for (int r = 0; r < 8; r++) acc[r] = make_float4(0.f,0.f,0.f,0.f);

        for (int kc = 0; kc < 512; kc += 16) {
            __syncthreads();
            #pragma unroll
            for (int u = 0; u < 2; u++) {
                const int idx = tid*2 + u;
                const int j = idx >> 2, kq = idx & 3;
                const float4 v = *(const float4*)(Wbase + (size_t)j*1024 + kc + kq*4);
                As[(kq*4+0)*132 + j] = v.x;
                As[(kq*4+1)*132 + j] = v.y;
                As[(kq*4+2)*132 + j] = v.z;
                As[(kq*4+3)*132 + j] = v.w;
            }
            {
                const int b = tid >> 2, kq = tid & 3;
                const float4 v = *(const float4*)(emb + (size_t)sTok[b]*512 + kc + kq*4);
                Bs[(kq*4+0)*68 + b] = v.x;
                Bs[(kq*4+1)*68 + b] = v.y;
                Bs[(kq*4+2)*68 + b] = v.z;
                Bs[(kq*4+3)*68 + b] = v.w;
            }
            __syncthreads();
            #pragma unroll
            for (int k = 0; k < 16; k++) {
                const float4 a0 = *(const float4*)(As + k*132 + ty*8);
                const float4 a1 = *(const float4*)(As + k*132 + ty*8 + 4);
                const float4 bq = *(const float4*)(Bs + k*68 + tx*4);
                const float ar[8] = {a0.x,a0.y,a0.z,a0.w,a1.x,a1.y,a1.z,a1.w};
                #pragma unroll
                for (int r = 0; r < 8; r++) fma4(ar[r], bq, acc[r]);
            }
        }
        const float* bias = ((gate==0) ? br : (gate==1) ? bz : bs) + wlo0 + jt*128 + ty*8;
        float* Pout = P + (((size_t)gate*256 + t)*512 + jt*128 + ty*8)*64 + tx*4;
        #pragma unroll
        for (int r = 0; r < 8; r++) {
            const float bb = bias[r];
            float4 o = acc[r];
            o.x += bb; o.y += bb; o.z += bb; o.w += bb;
            *(float4*)(Pout + (size_t)r*64) = o;
        }
    }
    __syncthreads();

    // ------------- stage recurrence weights (coalesced LDG) -------------
    for (int idx = tid; idx < 8192; idx += 256) {     // WRZ0: h-part K=512
        const int row = idx >> 9, k = idx & 511;
        const float* W = (row < 8) ? Wr : Wz;
        smem[OFF_WRZ0 + k*16 + row] = W[(size_t)(wlo0 + J0 + (row & 7))*1024 + 512 + k];
    }
    for (int idx = tid; idx < 4096; idx += 256) {     // WS0: h-part K=512
        const int row = idx >> 9, k = idx & 511;
        smem[OFF_WS0 + k*8 + row] = Ws[(size_t)(wlo0 + J0 + row)*1024 + 512 + k];
    }
    for (int idx = tid; idx < 16384; idx += 256) {    // WRZ1: full K=1024
        const int row = idx >> 10, k = idx & 1023;
        const float* W = (row < 8) ? Wr : Wz;
        smem[OFF_WRZ1 + k*16 + row] = W[(size_t)(wlo1 + J0 + (row & 7))*1024 + k];
    }
    for (int idx = tid; idx < 8192; idx += 256) {     // WS1: full K=1024
        const int row = idx >> 10, k = idx & 1023;
        smem[OFF_WS1 + k*8 + row] = Ws[(size_t)(wlo1 + J0 + row)*1024 + k];
    }
    gbar(d);   // P + h zeros visible everywhere

    // ------------- pipelined recurrence: layer0 @ t=rho, layer1 @ t=rho-1 -----
    for (int rho = 0; rho < 257; rho++) {
        const int cur = rho & 1;
        float* HT0c = dHT0[d][cur];       // h0 after t=rho-1 (== y0 for layer1)
        float* HT0n = dHT0[d][cur ^ 1];   // h0 write target
        const bool L0 = (rho < 256);
        const bool L1 = (rho >= 1);
        const int t0 = rho, t1 = rho - 1;

        if (L0) {
            gemv16<64>(smem + OFF_WRZ0, HT0c, HT0c, sRed, tid);
            __syncthreads();
            {   // reduce + sigmoid; u0 -> global, z0/h0old -> smem
                const int row = tid >> 4, b4 = (tid & 15) * 4;
                float4 s = make_float4(0.f,0.f,0.f,0.f);
                #pragma unroll
                for (int sp = 0; sp < 8; sp++) {
                    const float4 v = *(const float4*)(sRed + (sp*16 + row)*RSTR + b4);
                    s.x += v.x; s.y += v.y; s.z += v.z; s.w += v.w;
                }
                const int gate = row >> 3, j = row & 7;
                const float4 pre = *(const float4*)(P + (((size_t)gate*256 + t0)*512 + J0 + j)*64 + b4);
                float4 g;
                g.x = sigf(pre.x + s.x); g.y = sigf(pre.y + s.y);
                g.z = sigf(pre.z + s.z); g.w = sigf(pre.w + s.w);
                if (gate == 0) {
                    const float4 h = *(const float4*)(HT0c + (J0 + j)*64 + b4);
                    *(float4*)(sH0 + j*64 + b4) = h;
                    float4 u; u.x=g.x*h.x; u.y=g.y*h.y; u.z=g.z*h.z; u.w=g.w*h.w;
                    *(float4*)(UT0 + (J0 + j)*64 + b4) = u;
                } else {
                    *(float4*)(sZ0 + j*64 + b4) = g;
                }
            }
            __syncthreads();
        }
        if (L1) {
            gemv16<128>(smem + OFF_WRZ1, HT0c, HT1 - 512*64, sRed, tid);
            __syncthreads();
            {
                const int row = tid >> 4, b4 = (tid & 15) * 4;
                float4 s = make_float4(0.f,0.f,0.f,0.f);
                #pragma unroll
                for (int sp = 0; sp < 8; sp++) {
                    const float4 v = *(const float4*)(sRed + (sp*16 + row)*RSTR + b4);
                    s.x += v.x; s.y += v.y; s.z += v.z; s.w += v.w;
                }
                const int gate = row >> 3, j = row & 7;
                const float bb = ((gate == 0) ? br : bz)[wlo1 + J0 + j];
                float4 g;
                g.x = sigf(bb + s.x); g.y = sigf(bb + s.y);
                g.z = sigf(bb + s.z); g.w = sigf(bb + s.w);
                if (gate == 0) {
                    const float4 h = *(const float4*)(HT1 + (J0 + j)*64 + b4);
                    *(float4*)(sH1 + j*64 + b4) = h;
                    float4 u; u.x=g.x*h.x; u.y=g.y*h.y; u.z=g.z*h.z; u.w=g.w*h.w;
                    *(float4*)(UT1 + (J0 + j)*64 + b4) = u;
                } else {
                    *(float4*)(sZ1 + j*64 + b4) = g;
                }
            }
            __syncthreads();
        }
        gbar(d);   // u0, u1 visible to all CTAs

        if (L0) {
            gemv8<32>(smem + OFF_WS0, UT0, UT0, sRed, tid);
            __syncthreads();
            {   // reduce + tanh + h0 update
                const int row = tid >> 5, b2 = (tid & 31) * 2;
                float sx = 0.f, sy = 0.f;
                #pragma unroll
                for (int sp = 0; sp < 16; sp++) {
                    const float2 v = *(const float2*)(sRed + (sp*8 + row)*RSTR + b2);
                    sx += v.x; sy += v.y;
                }
                const float2 pre = *(const float2*)(P + (((size_t)2*256 + t0)*512 + J0 + row)*64 + b2);
                const float ssx = tanhf(pre.x + sx);
                const float ssy = tanhf(pre.y + sy);
                const float2 z = *(const float2*)(sZ0 + row*64 + b2);
                const float2 h = *(const float2*)(sH0 + row*64 + b2);
                const float hnx = z.x*h.x + (1.f - z.x)*ssx;
                const float hny = z.y*h.y + (1.f - z.y)*ssy;
                *(float2*)(HT0n + (J0 + row)*64 + b2) = make_float2(hnx, hny);
                if (rho == 255) {   // final layer-0 hidden
                    out[(size_t)OUT_SEQ + ((size_t)((d*2+0)*64) + b2    )*512 + J0 + row] = hnx;
                    out[(size_t)OUT_SEQ + ((size_t)((d*2+0)*64) + b2 + 1)*512 + J0 + row] = hny;
                }
            }
            __syncthreads();
        }
        if (L1) {
            gemv8<64>(smem + OFF_WS1, HT0c, UT1 - 512*64, sRed, tid);
            __syncthreads();
            {
                const int row = tid >> 5, b2 = (tid & 31) * 2;
                float sx = 0.f, sy = 0.f;
                #pragma unroll
                for (int sp = 0; sp < 16; sp++) {
                    const float2 v = *(const float2*)(sRed + (sp*8 + row)*RSTR + b2);
                    sx += v.x; sy += v.y;
                }
                const float bb = bs[wlo1 + J0 + row];
                const float ssx = tanhf(bb + sx);
                const float ssy = tanhf(bb + sy);
                const float2 z = *(const float2*)(sZ1 + row*64 + b2);
                const float2 h = *(const float2*)(sH1 + row*64 + b2);
                const float hnx = z.x*h.x + (1.f - z.x)*ssx;
                const float hny = z.y*h.y + (1.f - z.y)*ssy;
                *(float2*)(HT1 + (J0 + row)*64 + b2) = make_float2(hnx, hny);
                out[((size_t)t1*64 + b2    )*1024 + d*512 + J0 + row] = hnx;
                out[((size_t)t1*64 + b2 + 1)*1024 + d*512 + J0 + row] = hny;
                if (rho == 256) {   // final layer-1 hidden
                    out[(size_t)OUT_SEQ + ((size_t)((d*2+1)*64) + b2    )*512 + J0 + row] = hnx;
                    out[(size_t)OUT_SEQ + ((size_t)((d*2+1)*64) + b2 + 1)*512 + J0 + row] = hny;
                }
            }
            __syncthreads();
        }
        gbar(d);   // h0n, h1 visible for next round
    }
}

extern "C" void kernel_launch(void* const* d_in, const int* in_sizes, int n_in,
                              void* d_out, int out_size) {
    const int*   tokens = (const int*)  d_in[0];
    const float* emb    = (const float*)d_in[1];
    const float* Wr     = (const float*)d_in[2];
    const float* Wz     = (const float*)d_in[3];
    const float* Ws     = (const float*)d_in[4];
    const float* br     = (const float*)d_in[5];
    const float* bz     = (const float*)d_in[6];
    const float* bs     = (const float*)d_in[7];
    float* out = (float*)d_out;

    cudaFuncSetAttribute(bigru_kernel,
                         cudaFuncAttributeMaxDynamicSharedMemorySize,
                         SMEM_FLOATS * sizeof(float));
    bigru_kernel<<<128, 256, SMEM_FLOATS * sizeof(float)>>>(
        tokens, emb, Wr, Wz, Ws, br, bz, bs, out);
}

// round 10
// speedup vs baseline: 1.6841x; 1.1129x over previous
#include <cuda_runtime.h>
#include <math.h>

#define SQ 256
#define NB 64
#define NH 512
#define OUT_SEQ (SQ*NB*2*NH)   // 16,777,216 floats of [S,B,2H]; hidd follows

typedef unsigned long long ull;

// ---------------- device scratch (no allocs allowed) ----------------
// P[d][gate][t][j][b] : layer-0 x-side projections + bias (201 MB)
__device__ __align__(256) float dP[2u*3u*SQ*NH*NB];
__device__ __align__(256) float dHT0[2][2][NH*NB];   // layer-0 h, double buffered
__device__ __align__(256) float dHT1[2][NH*NB];      // layer-1 h
__device__ __align__(256) float dUT0[2][NH*NB];      // layer-0 u = r*h
__device__ __align__(256) float dUT1[2][NH*NB];      // layer-1 u
__device__ unsigned gBarCnt[2];
__device__ volatile unsigned gBarGen[2];

// Per-direction global barrier over 64 CTAs (sense-free generation counter).
// __threadfence() emits CCTL.IVALL on sm_103a -> post-barrier LDGs see other
// SMs' stores.
__device__ __forceinline__ void gbar(int d) {
    __syncthreads();
    if (threadIdx.x == 0) {
        __threadfence();
        unsigned gen = gBarGen[d];
        unsigned prev = atomicAdd(&gBarCnt[d], 1u);
        if (prev == 63u) {
            gBarCnt[d] = 0u;
            __threadfence();
            gBarGen[d] = gen + 1u;
        } else {
            while (gBarGen[d] == gen) { }
        }
        __threadfence();
    }
    __syncthreads();
}

__device__ __forceinline__ float sigf(float x) { return 1.0f / (1.0f + expf(-x)); }

// ---- packed fp32x2 helpers (sm_103a FFMA2; only reachable via PTX) ----
__device__ __forceinline__ void fma2(ull& c, ull a, ull b) {
    asm("fma.rn.f32x2 %0, %1, %2, %0;" : "+l"(c) : "l"(a), "l"(b));
}
__device__ __forceinline__ ull bcast2(float v) {
    ull r; asm("mov.b64 %0, {%1, %1};" : "=l"(r) : "f"(v)); return r;
}
__device__ __forceinline__ float2 unpk2(ull v) {
    float2 f; asm("mov.b64 {%0, %1}, %2;" : "=f"(f.x), "=f"(f.y) : "l"(v)); return f;
}

// ---------------- shared memory layout (floats) ----------------
//  proj phase overlay: As[16][132] at 0 (2112), Bs[16][68] at 2112 (1088)
//  sRed stride 68: 272 bytes/row -> float4-aligned, bank-shifted.
#define RSTR 68
#define OFF_WRZ0 0        // [k*16+row], k<512, rows 0-7=r 8-15=z (h-part)   8192
#define OFF_WS0  8192     // [k*8+row],  k<512                              4096
#define OFF_WRZ1 12288    // [k*16+row], k<1024 (x-part then h-part)       16384
#define OFF_WS1  28672    // [k*8+row],  k<1024                             8192
#define OFF_RED  36864    // K-split reduction buffer: 128 rows x 68        8704
#define OFF_Z0   45568
#define OFF_H0   46080
#define OFF_Z1   46592
#define OFF_H1   47104
#define SMEM_FLOATS 47616

// 16-row GEMV, 8 K-splits x KPS each. Wt: [k*16+row] smem. X chosen per split:
// k0 < 512 -> Xlo, else Xhi (pre-offset so X + k*64 is valid).
// acc packed along b (x pairs free from 128-bit loads; w broadcast-packed).
template<int KPS>
__device__ __forceinline__ void gemv16(const float* __restrict__ Wt,
                                       const float* __restrict__ Xlo,
                                       const float* __restrict__ Xhi,
                                       float* __restrict__ sRed, int tid)
{
    const int split = tid >> 5;
    const int rg = (tid >> 3) & 3;     // rows rg*4 .. rg*4+3
    const int bg = tid & 7;            // b = bg*8 .. bg*8+7
    const int k0 = split * KPS;
    const float* X = (k0 < 512) ? Xlo : Xhi;
    ull a[4][4];
    #pragma unroll
    for (int r = 0; r < 4; r++)
        #pragma unroll
        for (int q = 0; q < 4; q++) a[r][q] = 0ull;
    #pragma unroll 4
    for (int k = k0; k < k0 + KPS; k++) {
        const float4 w = *(const float4*)(Wt + k*16 + rg*4);
        const ull wp0 = bcast2(w.x), wp1 = bcast2(w.y),
                  wp2 = bcast2(w.z), wp3 = bcast2(w.w);
        const ulonglong2 xa = *(const ulonglong2*)(X + k*64 + bg*8);
        const ulonglong2 xb = *(const ulonglong2*)(X + k*64 + bg*8 + 4);
        fma2(a[0][0], wp0, xa.x); fma2(a[0][1], wp0, xa.y);
        fma2(a[0][2], wp0, xb.x); fma2(a[0][3], wp0, xb.y);
        fma2(a[1][0], wp1, xa.x); fma2(a[1][1], wp1, xa.y);
        fma2(a[1][2], wp1, xb.x); fma2(a[1][3], wp1, xb.y);
        fma2(a[2][0], wp2, xa.x); fma2(a[2][1], wp2, xa.y);
        fma2(a[2][2], wp2, xb.x); fma2(a[2][3], wp2, xb.y);
        fma2(a[3][0], wp3, xa.x); fma2(a[3][1], wp3, xa.y);
        fma2(a[3][2], wp3, xb.x); fma2(a[3][3], wp3, xb.y);
    }
    #pragma unroll
    for (int r = 0; r < 4; r++) {
        *(ulonglong2*)(sRed + (split*16 + rg*4 + r)*RSTR + bg*8)
            = make_ulonglong2(a[r][0], a[r][1]);
        *(ulonglong2*)(sRed + (split*16 + rg*4 + r)*RSTR + bg*8 + 4)
            = make_ulonglong2(a[r][2], a[r][3]);
    }
}

// 8-row GEMV, 16 K-splits x KPS each.
template<int KPS>
__device__ __forceinline__ void gemv8(const float* __restrict__ Wt,
                                      const float* __restrict__ Xlo,
                                      const float* __restrict__ Xhi,
                                      float* __restrict__ sRed, int tid)
{
    const int split = tid >> 4;
    const int rg = (tid >> 3) & 1;     // rows rg*4 .. rg*4+3
    const int bg = tid & 7;
    const int k0 = split * KPS;
    const float* X = (k0 < 512) ? Xlo : Xhi;
    ull a[4][4];
    #pragma unroll
    for (int r = 0; r < 4; r++)
        #pragma unroll
        for (int q = 0; q < 4; q++) a[r][q] = 0ull;
    #pragma unroll 4
    for (int k = k0; k < k0 + KPS; k++) {
        const float4 w = *(const float4*)(Wt + k*8 + rg*4);
        const ull wp0 = bcast2(w.x), wp1 = bcast2(w.y),
                  wp2 = bcast2(w.z), wp3 = bcast2(w.w);
        const ulonglong2 xa = *(const ulonglong2*)(X + k*64 + bg*8);
        const ulonglong2 xb = *(const ulonglong2*)(X + k*64 + bg*8 + 4);
        fma2(a[0][0], wp0, xa.x); fma2(a[0][1], wp0, xa.y);
        fma2(a[0][2], wp0, xb.x); fma2(a[0][3], wp0, xb.y);
        fma2(a[1][0], wp1, xa.x); fma2(a[1][1], wp1, xa.y);
        fma2(a[1][2], wp1, xb.x); fma2(a[1][3], wp1, xb.y);
        fma2(a[2][0], wp2, xa.x); fma2(a[2][1], wp2, xa.y);
        fma2(a[2][2], wp2, xb.x); fma2(a[2][3], wp2, xb.y);
        fma2(a[3][0], wp3, xa.x); fma2(a[3][1], wp3, xa.y);
        fma2(a[3][2], wp3, xb.x); fma2(a[3][3], wp3, xb.y);
    }
    #pragma unroll
    for (int r = 0; r < 4; r++) {
        *(ulonglong2*)(sRed + (split*8 + rg*4 + r)*RSTR + bg*8)
            = make_ulonglong2(a[r][0], a[r][1]);
        *(ulonglong2*)(sRed + (split*8 + rg*4 + r)*RSTR + bg*8 + 4)
            = make_ulonglong2(a[r][2], a[r][3]);
    }
}

__global__ void __launch_bounds__(256, 1)
bigru_kernel(const int*   __restrict__ tokens,
             const float* __restrict__ emb,
             const float* __restrict__ Wr,
             const float* __restrict__ Wz,
             const float* __restrict__ Ws,
             const float* __restrict__ br,
             const float* __restrict__ bz,
             const float* __restrict__ bs,
             float*       __restrict__ out)
{
    extern __shared__ float smem[];
    __shared__ int sTok[64];

    const int tid = threadIdx.x;
    const int d   = blockIdx.x >> 6;   // direction 0/1
    const int c   = blockIdx.x & 63;   // cta within direction
    const int J0  = c * 8;             // owned hidden-unit slice (both layers)

    float* P   = dP + (size_t)d * 3u * SQ * NH * NB;
    float* HT1 = dHT1[d];
    float* UT0 = dUT0[d];
    float* UT1 = dUT1[d];

    const int wlo0 = (d*2 + 0) * 512;
    const int wlo1 = (d*2 + 1) * 512;

    float* As   = smem;
    float* Bs   = smem + 2112;
    float* sRed = smem + OFF_RED;
    float* sZ0  = smem + OFF_Z0;
    float* sH0  = smem + OFF_H0;
    float* sZ1  = smem + OFF_Z1;
    float* sH1  = smem + OFF_H1;

    // zero own h slices (h0 = h1 = 0); published by the proj-end gbar
    for (int i = tid; i < 512; i += 256) {
        dHT0[d][0][J0*64 + i] = 0.0f;
        dHT0[d][1][J0*64 + i] = 0.0f;
        HT1[J0*64 + i] = 0.0f;
    }

    // ------------- layer-0 input projections: P[gate][t][j][b] -------------
    // 3 gates x 4 j-tiles(128) x 256 t = 3072 tiles; 48 per CTA.
    // acc packed along j-rows: As row-pairs come free from LDS.128 halves,
    // only the 4 Bs values need broadcast-packing.
    for (int tb = 0; tb < 48; tb++) {
        const int tile = c * 48 + tb;
        const int t    = tile & 255;
        const int grp  = tile >> 8;     // 0..11
        const int gate = grp >> 2;
        const int jt   = grp & 3;
        const float* W = (gate == 0) ? Wr : (gate == 1) ? Wz : Ws;
        const float* Wbase = W + (size_t)(wlo0 + jt*128) * 1024;
        const int ty = tid >> 4, tx = tid & 15;

        if (tid < 64) {
            const int tp = d ? (255 - t) : t;
            sTok[tid] = tokens[tp*64 + tid];
        }

        ull acc[4][4];   // [row-pair][b]; pair = rows (ty*8+2rp, ty*8+2rp+1)
        #pragma unroll
        for (int rp = 0; rp < 4; rp++)
            #pragma unroll
            for (int b = 0; b < 4; b++) acc[rp][b] = 0ull;

        for (int kc = 0; kc < 512; kc += 16) {
            __syncthreads();
            #pragma unroll
            for (int u = 0; u < 2; u++) {
                const int idx = tid*2 + u;
                const int j = idx >> 2, kq = idx & 3;
                const float4 v = *(const float4*)(Wbase + (size_t)j*1024 + kc + kq*4);
                As[(kq*4+0)*132 + j] = v.x;
                As[(kq*4+1)*132 + j] = v.y;
                As[(kq*4+2)*132 + j] = v.z;
                As[(kq*4+3)*132 + j] = v.w;
            }
            {
                const int b = tid >> 2, kq = tid & 3;
                const float4 v = *(const float4*)(emb + (size_t)sTok[b]*512 + kc + kq*4);
                Bs[(kq*4+0)*68 + b] = v.x;
                Bs[(kq*4+1)*68 + b] = v.y;
                Bs[(kq*4+2)*68 + b] = v.z;
                Bs[(kq*4+3)*68 + b] = v.w;
            }
            __syncthreads();
            #pragma unroll
            for (int k = 0; k < 16; k++) {
                const ulonglong2 a01 = *(const ulonglong2*)(As + k*132 + ty*8);
                const ulonglong2 a23 = *(const ulonglong2*)(As + k*132 + ty*8 + 4);
                const float4 bq = *(const float4*)(Bs + k*68 + tx*4);
                const ull b0 = bcast2(bq.x), b1 = bcast2(bq.y),
                          b2 = bcast2(bq.z), b3 = bcast2(bq.w);
                fma2(acc[0][0], a01.x, b0); fma2(acc[0][1], a01.x, b1);
                fma2(acc[0][2], a01.x, b2); fma2(acc[0][3], a01.x, b3);
                fma2(acc[1][0], a01.y, b0); fma2(acc[1][1], a01.y, b1);
                fma2(acc[1][2], a01.y, b2); fma2(acc[1][3], a01.y, b3);
                fma2(acc[2][0], a23.x, b0); fma2(acc[2][1], a23.x, b1);
                fma2(acc[2][2], a23.x, b2); fma2(acc[2][3], a23.x, b3);
                fma2(acc[3][0], a23.y, b0); fma2(acc[3][1], a23.y, b1);
                fma2(acc[3][2], a23.y, b2); fma2(acc[3][3], a23.y, b3);
            }
        }
        const float* bias = ((gate==0) ? br : (gate==1) ? bz : bs) + wlo0 + jt*128 + ty*8;
        float* Pout = P + (((size_t)gate*256 + t)*512 + jt*128 + ty*8)*64 + tx*4;
        #pragma unroll
        for (int rp = 0; rp < 4; rp++) {
            const float2 u0 = unpk2(acc[rp][0]);
            const float2 u1 = unpk2(acc[rp][1]);
            const float2 u2 = unpk2(acc[rp][2]);
            const float2 u3 = unpk2(acc[rp][3]);
            const float be = bias[rp*2], bo = bias[rp*2+1];
            float4 oe = make_float4(u0.x + be, u1.x + be, u2.x + be, u3.x + be);
            float4 oo = make_float4(u0.y + bo, u1.y + bo, u2.y + bo, u3.y + bo);
            *(float4*)(Pout + (size_t)(rp*2    )*64) = oe;
            *(float4*)(Pout + (size_t)(rp*2 + 1)*64) = oo;
        }
    }
    __syncthreads();

    // ------------- stage recurrence weights (coalesced LDG) -------------
    for (int idx = tid; idx < 8192; idx += 256) {     // WRZ0: h-part K=512
        const int row = idx >> 9, k = idx & 511;
        const float* W = (row < 8) ? Wr : Wz;
        smem[OFF_WRZ0 + k*16 + row] = W[(size_t)(wlo0 + J0 + (row & 7))*1024 + 512 + k];
    }
    for (int idx = tid; idx < 4096; idx += 256) {     // WS0: h-part K=512
        const int row = idx >> 9, k = idx & 511;
        smem[OFF_WS0 + k*8 + row] = Ws[(size_t)(wlo0 + J0 + row)*1024 + 512 + k];
    }
    for (int idx = tid; idx < 16384; idx += 256) {    // WRZ1: full K=1024
        const int row = idx >> 10, k = idx & 1023;
        const float* W = (row < 8) ? Wr : Wz;
        smem[OFF_WRZ1 + k*16 + row] = W[(size_t)(wlo1 + J0 + (row & 7))*1024 + k];
    }
    for (int idx = tid; idx < 8192; idx += 256) {     // WS1: full K=1024
        const int row = idx >> 10, k = idx & 1023;
        smem[OFF_WS1 + k*8 + row] = Ws[(size_t)(wlo1 + J0 + row)*1024 + k];
    }
    gbar(d);   // P + h zeros visible everywhere

    // ------------- pipelined recurrence: layer0 @ t=rho, layer1 @ t=rho-1 -----
    for (int rho = 0; rho < 257; rho++) {
        const int cur = rho & 1;
        float* HT0c = dHT0[d][cur];       // h0 after t=rho-1 (== y0 for layer1)
        float* HT0n = dHT0[d][cur ^ 1];   // h0 write target
        const bool L0 = (rho < 256);
        const bool L1 = (rho >= 1);
        const int t0 = rho, t1 = rho - 1;

        if (L0) {
            gemv16<64>(smem + OFF_WRZ0, HT0c, HT0c, sRed, tid);
            __syncthreads();
            {   // reduce + sigmoid; u0 -> global, z0/h0old -> smem
                const int row = tid >> 4, b4 = (tid & 15) * 4;
                float4 s = make_float4(0.f,0.f,0.f,0.f);
                #pragma unroll
                for (int sp = 0; sp < 8; sp++) {
                    const float4 v = *(const float4*)(sRed + (sp*16 + row)*RSTR + b4);
                    s.x += v.x; s.y += v.y; s.z += v.z; s.w += v.w;
                }
                const int gate = row >> 3, j = row & 7;
                const float4 pre = *(const float4*)(P + (((size_t)gate*256 + t0)*512 + J0 + j)*64 + b4);
                float4 g;
                g.x = sigf(pre.x + s.x); g.y = sigf(pre.y + s.y);
                g.z = sigf(pre.z + s.z); g.w = sigf(pre.w + s.w);
                if (gate == 0) {
                    const float4 h = *(const float4*)(HT0c + (J0 + j)*64 + b4);
                    *(float4*)(sH0 + j*64 + b4) = h;
                    float4 u; u.x=g.x*h.x; u.y=g.y*h.y; u.z=g.z*h.z; u.w=g.w*h.w;
                    *(float4*)(UT0 + (J0 + j)*64 + b4) = u;
                } else {
                    *(float4*)(sZ0 + j*64 + b4) = g;
                }
            }
            __syncthreads();
        }
        if (L1) {
            gemv16<128>(smem + OFF_WRZ1, HT0c, HT1 - 512*64, sRed, tid);
            __syncthreads();
            {
                const int row = tid >> 4, b4 = (tid & 15) * 4;
                float4 s = make_float4(0.f,0.f,0.f,0.f);
                #pragma unroll
                for (int sp = 0; sp < 8; sp++) {
                    const float4 v = *(const float4*)(sRed + (sp*16 + row)*RSTR + b4);
                    s.x += v.x; s.y += v.y; s.z += v.z; s.w += v.w;
                }
                const int gate = row >> 3, j = row & 7;
                const float bb = ((gate == 0) ? br : bz)[wlo1 + J0 + j];
                float4 g;
                g.x = sigf(bb + s.x); g.y = sigf(bb + s.y);
                g.z = sigf(bb + s.z); g.w = sigf(bb + s.w);
                if (gate == 0) {
                    const float4 h = *(const float4*)(HT1 + (J0 + j)*64 + b4);
                    *(float4*)(sH1 + j*64 + b4) = h;
                    float4 u; u.x=g.x*h.x; u.y=g.y*h.y; u.z=g.z*h.z; u.w=g.w*h.w;
                    *(float4*)(UT1 + (J0 + j)*64 + b4) = u;
                } else {
                    *(float4*)(sZ1 + j*64 + b4) = g;
                }
            }
            __syncthreads();
        }
        gbar(d);   // u0, u1 visible to all CTAs

        if (L0) {
            gemv8<32>(smem + OFF_WS0, UT0, UT0, sRed, tid);
            __syncthreads();
            {   // reduce + tanh + h0 update
                const int row = tid >> 5, b2 = (tid & 31) * 2;
                float sx = 0.f, sy = 0.f;
                #pragma unroll
                for (int sp = 0; sp < 16; sp++) {
                    const float2 v = *(const float2*)(sRed + (sp*8 + row)*RSTR + b2);
                    sx += v.x; sy += v.y;
                }
                const float2 pre = *(const float2*)(P + (((size_t)2*256 + t0)*512 + J0 + row)*64 + b2);
                const float ssx = tanhf(pre.x + sx);
                const float ssy = tanhf(pre.y + sy);
                const float2 z = *(const float2*)(sZ0 + row*64 + b2);
                const float2 h = *(const float2*)(sH0 + row*64 + b2);
                const float hnx = z.x*h.x + (1.f - z.x)*ssx;
                const float hny = z.y*h.y + (1.f - z.y)*ssy;
                *(float2*)(HT0n + (J0 + row)*64 + b2) = make_float2(hnx, hny);
                if (rho == 255) {   // final layer-0 hidden
                    out[(size_t)OUT_SEQ + ((size_t)((d*2+0)*64) + b2    )*512 + J0 + row] = hnx;
                    out[(size_t)OUT_SEQ + ((size_t)((d*2+0)*64) + b2 + 1)*512 + J0 + row] = hny;
                }
            }
            __syncthreads();
        }
        if (L1) {
            gemv8<64>(smem + OFF_WS1, HT0c, UT1 - 512*64, sRed, tid);
            __syncthreads();
            {
                const int row = tid >> 5, b2 = (tid & 31) * 2;
                float sx = 0.f, sy = 0.f;
                #pragma unroll
                for (int sp = 0; sp < 16; sp++) {
                    const float2 v = *(const float2*)(sRed + (sp*8 + row)*RSTR + b2);
                    sx += v.x; sy += v.y;
                }
                const float bb = bs[wlo1 + J0 + row];
                const float ssx = tanhf(bb + sx);
                const float ssy = tanhf(bb + sy);
                const float2 z = *(const float2*)(sZ1 + row*64 + b2);
                const float2 h = *(const float2*)(sH1 + row*64 + b2);
                const float hnx = z.x*h.x + (1.f - z.x)*ssx;
                const float hny = z.y*h.y + (1.f - z.y)*ssy;
                *(float2*)(HT1 + (J0 + row)*64 + b2) = make_float2(hnx, hny);
                out[((size_t)t1*64 + b2    )*1024 + d*512 + J0 + row] = hnx;
                out[((size_t)t1*64 + b2 + 1)*1024 + d*512 + J0 + row] = hny;
                if (rho == 256) {   // final layer-1 hidden
                    out[(size_t)OUT_SEQ + ((size_t)((d*2+1)*64) + b2    )*512 + J0 + row] = hnx;
                    out[(size_t)OUT_SEQ + ((size_t)((d*2+1)*64) + b2 + 1)*512 + J0 + row] = hny;
                }
            }
            __syncthreads();
        }
        gbar(d);   // h0n, h1 visible for next round
    }
}

extern "C" void kernel_launch(void* const* d_in, const int* in_sizes, int n_in,
                              void* d_out, int out_size) {
    const int*   tokens = (const int*)  d_in[0];
    const float* emb    = (const float*)d_in[1];
    const float* Wr     = (const float*)d_in[2];
    const float* Wz     = (const float*)d_in[3];
    const float* Ws     = (const float*)d_in[4];
    const float* br     = (const float*)d_in[5];
    const float* bz     = (const float*)d_in[6];
    const float* bs     = (const float*)d_in[7];
    float* out = (float*)d_out;

    cudaFuncSetAttribute(bigru_kernel,
                         cudaFuncAttributeMaxDynamicSharedMemorySize,
                         SMEM_FLOATS * sizeof(float));
    bigru_kernel<<<128, 256, SMEM_FLOATS * sizeof(float)>>>(
        tokens, emb, Wr, Wz, Ws, br, bz, bs, out);
}

// round 13
// speedup vs baseline: 1.8675x; 1.1089x over previous
#include <cuda_runtime.h>
#include <math.h>

#define SQ 256
#define NB 64
#define NH 512
#define OUT_SEQ (SQ*NB*2*NH)   // 16,777,216 floats of [S,B,2H]; hidd follows

typedef unsigned long long ull;

// ---------------- device scratch (no allocs allowed) ----------------
__device__ __align__(256) float dP[2u*3u*SQ*NH*NB];  // layer-0 x-proj + bias
__device__ __align__(256) float dHT0[2][2][NH*NB];   // layer-0 h, double buffered
__device__ __align__(256) float dHT1[2][NH*NB];      // layer-1 h
__device__ __align__(256) float dUT0[2][NH*NB];      // layer-0 u = r*h
__device__ __align__(256) float dUT1[2][NH*NB];      // layer-1 u
__device__ unsigned gBarCnt[2];
__device__ volatile unsigned gBarGen[2];

// Per-direction global barrier over 64 CTAs (sense-free generation counter).
// __threadfence() emits CCTL.IVALL on sm_103a -> post-barrier LDGs see other
// SMs' stores.
__device__ __forceinline__ void gbar(int d) {
    __syncthreads();
    if (threadIdx.x == 0) {
        __threadfence();
        unsigned gen = gBarGen[d];
        unsigned prev = atomicAdd(&gBarCnt[d], 1u);
        if (prev == 63u) {
            gBarCnt[d] = 0u;
            __threadfence();
            gBarGen[d] = gen + 1u;
        } else {
            while (gBarGen[d] == gen) { }
        }
        __threadfence();
    }
    __syncthreads();
}

__device__ __forceinline__ float sigf(float x) { return 1.0f / (1.0f + expf(-x)); }

// ---- packed fp32x2 helpers (FFMA2 via PTX: halves issue slots) ----
__device__ __forceinline__ void fma2(ull& c, ull a, ull b) {
    asm("fma.rn.f32x2 %0, %1, %2, %0;" : "+l"(c) : "l"(a), "l"(b));
}
__device__ __forceinline__ ull bcast2(float v) {
    ull r; asm("mov.b64 %0, {%1, %1};" : "=l"(r) : "f"(v)); return r;
}
__device__ __forceinline__ float2 unpk2(ull v) {
    float2 f; asm("mov.b64 {%0, %1}, %2;" : "=f"(f.x), "=f"(f.y) : "l"(v)); return f;
}

// ---------------- shared memory layout (floats) ----------------
//  proj overlay: As[16][132] at 0 (2112), Bs0 at 2112 (1088), Bs1 at 3200 (1088)
//  sRed stride 68: 272 B/row -> float4-aligned, bank-shifted.
#define RSTR 68
#define OFF_WRZ0 0        // [k*16+row], k<512                              8192
#define OFF_WS0  8192     // [k*8+row],  k<512                              4096
#define OFF_WRZ1 12288    // [k*16+row], k<1024                            16384
#define OFF_WS1  28672    // [k*8+row],  k<1024                             8192
#define OFF_RED  36864    // 256 rows x 68                                 17408
#define OFF_Z0   54272
#define OFF_H0   54784
#define OFF_Z1   55296
#define OFF_H1   55808
#define SMEM_FLOATS 56320   // 225,280 bytes

// 16-row GEMV, 16 K-splits x KPS each (512 threads).
// k0 < 512 -> Xlo, else Xhi (pre-offset so X + k*64 is valid).
template<int KPS>
__device__ __forceinline__ void gemv16(const float* __restrict__ Wt,
                                       const float* __restrict__ Xlo,
                                       const float* __restrict__ Xhi,
                                       float* __restrict__ sRed, int tid)
{
    const int split = tid >> 5;        // 0..15
    const int rg = (tid >> 3) & 3;     // rows rg*4 .. rg*4+3
    const int bg = tid & 7;            // b = bg*8 .. bg*8+7
    const int k0 = split * KPS;
    const float* X = (k0 < 512) ? Xlo : Xhi;
    ull a[4][4];
    #pragma unroll
    for (int r = 0; r < 4; r++)
        #pragma unroll
        for (int q = 0; q < 4; q++) a[r][q] = 0ull;
    #pragma unroll 4
    for (int k = k0; k < k0 + KPS; k++) {
        const float4 w = *(const float4*)(Wt + k*16 + rg*4);
        const ull wp0 = bcast2(w.x), wp1 = bcast2(w.y),
                  wp2 = bcast2(w.z), wp3 = bcast2(w.w);
        const ulonglong2 xa = *(const ulonglong2*)(X + k*64 + bg*8);
        const ulonglong2 xb = *(const ulonglong2*)(X + k*64 + bg*8 + 4);
        fma2(a[0][0], wp0, xa.x); fma2(a[0][1], wp0, xa.y);
        fma2(a[0][2], wp0, xb.x); fma2(a[0][3], wp0, xb.y);
        fma2(a[1][0], wp1, xa.x); fma2(a[1][1], wp1, xa.y);
        fma2(a[1][2], wp1, xb.x); fma2(a[1][3], wp1, xb.y);
        fma2(a[2][0], wp2, xa.x); fma2(a[2][1], wp2, xa.y);
        fma2(a[2][2], wp2, xb.x); fma2(a[2][3], wp2, xb.y);
        fma2(a[3][0], wp3, xa.x); fma2(a[3][1], wp3, xa.y);
        fma2(a[3][2], wp3, xb.x); fma2(a[3][3], wp3, xb.y);
    }
    #pragma unroll
    for (int r = 0; r < 4; r++) {
        *(ulonglong2*)(sRed + (split*16 + rg*4 + r)*RSTR + bg*8)
            = make_ulonglong2(a[r][0], a[r][1]);
        *(ulonglong2*)(sRed + (split*16 + rg*4 + r)*RSTR + bg*8 + 4)
            = make_ulonglong2(a[r][2], a[r][3]);
    }
}

// 8-row GEMV, 32 K-splits x KPS each (512 threads).
template<int KPS>
__device__ __forceinline__ void gemv8(const float* __restrict__ Wt,
                                      const float* __restrict__ Xlo,
                                      const float* __restrict__ Xhi,
                                      float* __restrict__ sRed, int tid)
{
    const int split = tid >> 4;        // 0..31
    const int rg = (tid >> 3) & 1;     // rows rg*4 .. rg*4+3
    const int bg = tid & 7;
    const int k0 = split * KPS;
    const float* X = (k0 < 512) ? Xlo : Xhi;
    ull a[4][4];
    #pragma unroll
    for (int r = 0; r < 4; r++)
        #pragma unroll
        for (int q = 0; q < 4; q++) a[r][q] = 0ull;
    #pragma unroll 4
    for (int k = k0; k < k0 + KPS; k++) {
        const float4 w = *(const float4*)(Wt + k*8 + rg*4);
        const ull wp0 = bcast2(w.x), wp1 = bcast2(w.y),
                  wp2 = bcast2(w.z), wp3 = bcast2(w.w);
        const ulonglong2 xa = *(const ulonglong2*)(X + k*64 + bg*8);
        const ulonglong2 xb = *(const ulonglong2*)(X + k*64 + bg*8 + 4);
        fma2(a[0][0], wp0, xa.x); fma2(a[0][1], wp0, xa.y);
        fma2(a[0][2], wp0, xb.x); fma2(a[0][3], wp0, xb.y);
        fma2(a[1][0], wp1, xa.x); fma2(a[1][1], wp1, xa.y);
        fma2(a[1][2], wp1, xb.x); fma2(a[1][3], wp1, xb.y);
        fma2(a[2][0], wp2, xa.x); fma2(a[2][1], wp2, xa.y);
        fma2(a[2][2], wp2, xb.x); fma2(a[2][3], wp2, xb.y);
        fma2(a[3][0], wp3, xa.x); fma2(a[3][1], wp3, xa.y);
        fma2(a[3][2], wp3, xb.x); fma2(a[3][3], wp3, xb.y);
    }
    #pragma unroll
    for (int r = 0; r < 4; r++) {
        *(ulonglong2*)(sRed + (split*8 + rg*4 + r)*RSTR + bg*8)
            = make_ulonglong2(a[r][0], a[r][1]);
        *(ulonglong2*)(sRed + (split*8 + rg*4 + r)*RSTR + bg*8 + 4)
            = make_ulonglong2(a[r][2], a[r][3]);
    }
}

__global__ void __launch_bounds__(512, 1)
bigru_kernel(const int*   __restrict__ tokens,
             const float* __restrict__ emb,
             const float* __restrict__ Wr,
             const float* __restrict__ Wz,
             const float* __restrict__ Ws,
             const float* __restrict__ br,
             const float* __restrict__ bz,
             const float* __restrict__ bs,
             float*       __restrict__ out)
{
    extern __shared__ float smem[];
    __shared__ int sTok[128];

    const int tid = threadIdx.x;
    const int d   = blockIdx.x >> 6;   // direction 0/1
    const int c   = blockIdx.x & 63;   // cta within direction
    const int J0  = c * 8;             // owned hidden-unit slice (both layers)

    float* P   = dP + (size_t)d * 3u * SQ * NH * NB;
    float* HT1 = dHT1[d];
    float* UT0 = dUT0[d];
    float* UT1 = dUT1[d];

    const int wlo0 = (d*2 + 0) * 512;
    const int wlo1 = (d*2 + 1) * 512;

    float* As   = smem;
    float* sRed = smem + OFF_RED;
    float* sZ0  = smem + OFF_Z0;
    float* sH0  = smem + OFF_H0;
    float* sZ1  = smem + OFF_Z1;
    float* sH1  = smem + OFF_H1;

    // zero own h slices (h0 = h1 = 0); published by the proj-end gbar
    if (tid < 512) {
        dHT0[d][0][J0*64 + tid] = 0.0f;
        dHT0[d][1][J0*64 + tid] = 0.0f;
        HT1[J0*64 + tid] = 0.0f;
    }

    // ------------- layer-0 input projections: P[gate][t][j][b] -------------
    // t-paired double-tiles: both 256-thread halves share one As weight tile,
    // each computes a different t. 3 gates x 4 jt x 128 t-pairs = 1536; 24/CTA.
    {
        const int half = tid >> 8;          // 0/1 -> t = 2u+half
        const int htid = tid & 255;
        float* Bs = smem + 2112 + half*1088;
        const int ty = htid >> 4, tx = htid & 15;

        for (int tb = 0; tb < 24; tb++) {
            const int tile = c * 24 + tb;
            const int up   = tile & 127;
            const int grp  = tile >> 7;     // 0..11
            const int gate = grp >> 2;
            const int jt   = grp & 3;
            const int t    = up*2 + half;
            const float* W = (gate == 0) ? Wr : (gate == 1) ? Wz : Ws;
            const float* Wbase = W + (size_t)(wlo0 + jt*128) * 1024;

            if (htid < 64) {
                const int tp = d ? (255 - t) : t;
                sTok[half*64 + htid] = tokens[tp*64 + htid];
            }

            ull acc[4][4];   // [row-pair][b]
            #pragma unroll
            for (int rp = 0; rp < 4; rp++)
                #pragma unroll
                for (int b = 0; b < 4; b++) acc[rp][b] = 0ull;

            for (int kc = 0; kc < 512; kc += 16) {
                __syncthreads();
                {   // As: all 512 threads, one float4 each (128j x 16k)
                    const int j = tid >> 2, kq = tid & 3;
                    const float4 v = *(const float4*)(Wbase + (size_t)j*1024 + kc + kq*4);
                    As[(kq*4+0)*132 + j] = v.x;
                    As[(kq*4+1)*132 + j] = v.y;
                    As[(kq*4+2)*132 + j] = v.z;
                    As[(kq*4+3)*132 + j] = v.w;
                }
                {   // Bs: per half (16k x 64b)
                    const int b = htid >> 2, kq = htid & 3;
                    const float4 v = *(const float4*)(emb + (size_t)sTok[half*64+b]*512 + kc + kq*4);
                    Bs[(kq*4+0)*68 + b] = v.x;
                    Bs[(kq*4+1)*68 + b] = v.y;
                    Bs[(kq*4+2)*68 + b] = v.z;
                    Bs[(kq*4+3)*68 + b] = v.w;
                }
                __syncthreads();
                #pragma unroll
                for (int k = 0; k < 16; k++) {
                    const ulonglong2 a01 = *(const ulonglong2*)(As + k*132 + ty*8);
                    const ulonglong2 a23 = *(const ulonglong2*)(As + k*132 + ty*8 + 4);
                    const float4 bq = *(const float4*)(Bs + k*68 + tx*4);
                    const ull b0 = bcast2(bq.x), b1 = bcast2(bq.y),
                              b2 = bcast2(bq.z), b3 = bcast2(bq.w);
                    fma2(acc[0][0], a01.x, b0); fma2(acc[0][1], a01.x, b1);
                    fma2(acc[0][2], a01.x, b2); fma2(acc[0][3], a01.x, b3);
                    fma2(acc[1][0], a01.y, b0); fma2(acc[1][1], a01.y, b1);
                    fma2(acc[1][2], a01.y, b2); fma2(acc[1][3], a01.y, b3);
                    fma2(acc[2][0], a23.x, b0); fma2(acc[2][1], a23.x, b1);
                    fma2(acc[2][2], a23.x, b2); fma2(acc[2][3], a23.x, b3);
                    fma2(acc[3][0], a23.y, b0); fma2(acc[3][1], a23.y, b1);
                    fma2(acc[3][2], a23.y, b2); fma2(acc[3][3], a23.y, b3);
                }
            }
            const float* bias = ((gate==0) ? br : (gate==1) ? bz : bs) + wlo0 + jt*128 + ty*8;
            float* Pout = P + (((size_t)gate*256 + t)*512 + jt*128 + ty*8)*64 + tx*4;
            #pragma unroll
            for (int rp = 0; rp < 4; rp++) {
                const float2 u0 = unpk2(acc[rp][0]);
                const float2 u1 = unpk2(acc[rp][1]);
                const float2 u2 = unpk2(acc[rp][2]);
                const float2 u3 = unpk2(acc[rp][3]);
                const float be = bias[rp*2], bo = bias[rp*2+1];
                float4 oe = make_float4(u0.x + be, u1.x + be, u2.x + be, u3.x + be);
                float4 oo = make_float4(u0.y + bo, u1.y + bo, u2.y + bo, u3.y + bo);
                *(float4*)(Pout + (size_t)(rp*2    )*64) = oe;
                *(float4*)(Pout + (size_t)(rp*2 + 1)*64) = oo;
            }
        }
    }
    __syncthreads();

    // ------------- stage recurrence weights (coalesced LDG) -------------
    for (int idx = tid; idx < 8192; idx += 512) {     // WRZ0: h-part K=512
        const int row = idx >> 9, k = idx & 511;
        const float* W = (row < 8) ? Wr : Wz;
        smem[OFF_WRZ0 + k*16 + row] = W[(size_t)(wlo0 + J0 + (row & 7))*1024 + 512 + k];
    }
    for (int idx = tid; idx < 4096; idx += 512) {     // WS0: h-part K=512
        const int row = idx >> 9, k = idx & 511;
        smem[OFF_WS0 + k*8 + row] = Ws[(size_t)(wlo0 + J0 + row)*1024 + 512 + k];
    }
    for (int idx = tid; idx < 16384; idx += 512) {    // WRZ1: full K=1024
        const int row = idx >> 10, k = idx & 1023;
        const float* W = (row < 8) ? Wr : Wz;
        smem[OFF_WRZ1 + k*16 + row] = W[(size_t)(wlo1 + J0 + (row & 7))*1024 + k];
    }
    for (int idx = tid; idx < 8192; idx += 512) {     // WS1: full K=1024
        const int row = idx >> 10, k = idx & 1023;
        smem[OFF_WS1 + k*8 + row] = Ws[(size_t)(wlo1 + J0 + row)*1024 + k];
    }
    gbar(d);   // P + h zeros visible everywhere

    // ------------- pipelined recurrence: layer0 @ t=rho, layer1 @ t=rho-1 -----
    for (int rho = 0; rho < 257; rho++) {
        const int cur = rho & 1;
        float* HT0c = dHT0[d][cur];       // h0 after t=rho-1 (== y0 for layer1)
        float* HT0n = dHT0[d][cur ^ 1];   // h0 write target
        const bool L0 = (rho < 256);
        const bool L1 = (rho >= 1);
        const int t0 = rho, t1 = rho - 1;

        if (L0) {
            gemv16<32>(smem + OFF_WRZ0, HT0c, HT0c, sRed, tid);
            __syncthreads();
            {   // reduce + sigmoid; u0 -> global, z0/h0old -> smem
                const int row = tid >> 5, b2 = (tid & 31) * 2;
                float sx = 0.f, sy = 0.f;
                #pragma unroll
                for (int sp = 0; sp < 16; sp++) {
                    const float2 v = *(const float2*)(sRed + (sp*16 + row)*RSTR + b2);
                    sx += v.x; sy += v.y;
                }
                const int gate = row >> 3, j = row & 7;
                const float2 pre = *(const float2*)(P + (((size_t)gate*256 + t0)*512 + J0 + j)*64 + b2);
                const float gx = sigf(pre.x + sx);
                const float gy = sigf(pre.y + sy);
                if (gate == 0) {
                    const float2 h = *(const float2*)(HT0c + (J0 + j)*64 + b2);
                    *(float2*)(sH0 + j*64 + b2) = h;
                    *(float2*)(UT0 + (J0 + j)*64 + b2) = make_float2(gx*h.x, gy*h.y);
                } else {
                    *(float2*)(sZ0 + j*64 + b2) = make_float2(gx, gy);
                }
            }
            __syncthreads();
        }
        if (L1) {
            gemv16<64>(smem + OFF_WRZ1, HT0c, HT1 - 512*64, sRed, tid);
            __syncthreads();
            {
                const int row = tid >> 5, b2 = (tid & 31) * 2;
                float sx = 0.f, sy = 0.f;
                #pragma unroll
                for (int sp = 0; sp < 16; sp++) {
                    const float2 v = *(const float2*)(sRed + (sp*16 + row)*RSTR + b2);
                    sx += v.x; sy += v.y;
                }
                const int gate = row >> 3, j = row & 7;
                const float bb = ((gate == 0) ? br : bz)[wlo1 + J0 + j];
                const float gx = sigf(bb + sx);
                const float gy = sigf(bb + sy);
                if (gate == 0) {
                    const float2 h = *(const float2*)(HT1 + (J0 + j)*64 + b2);
                    *(float2*)(sH1 + j*64 + b2) = h;
                    *(float2*)(UT1 + (J0 + j)*64 + b2) = make_float2(gx*h.x, gy*h.y);
                } else {
                    *(float2*)(sZ1 + j*64 + b2) = make_float2(gx, gy);
                }
            }
            __syncthreads();
        }
        gbar(d);   // u0, u1 visible to all CTAs

        if (L0) {
            gemv8<16>(smem + OFF_WS0, UT0, UT0, sRed, tid);
            __syncthreads();
            {   // reduce + tanh + h0 update
                const int row = tid >> 6, b = tid & 63;
                float s = 0.f;
                #pragma unroll
                for (int sp = 0; sp < 32; sp++)
                    s += sRed[(sp*8 + row)*RSTR + b];
                const float pre = P[(((size_t)2*256 + t0)*512 + J0 + row)*64 + b];
                const float ss = tanhf(pre + s);
                const float z = sZ0[row*64 + b];
                const float h = sH0[row*64 + b];
                const float hn = z*h + (1.f - z)*ss;
                HT0n[(J0 + row)*64 + b] = hn;
                if (rho == 255)   // final layer-0 hidden
                    out[(size_t)OUT_SEQ + ((size_t)((d*2+0)*64) + b)*512 + J0 + row] = hn;
            }
            __syncthreads();
        }
        if (L1) {
            gemv8<32>(smem + OFF_WS1, HT0c, UT1 - 512*64, sRed, tid);
            __syncthreads();
            {
                const int row = tid >> 6, b = tid & 63;
                float s = 0.f;
                #pragma unroll
                for (int sp = 0; sp < 32; sp++)
                    s += sRed[(sp*8 + row)*RSTR + b];
                const float bb = bs[wlo1 + J0 + row];
                const float ss = tanhf(bb + s);
                const float z = sZ1[row*64 + b];
                const float h = sH1[row*64 + b];
                const float hn = z*h + (1.f - z)*ss;
                HT1[(J0 + row)*64 + b] = hn;
                out[((size_t)t1*64 + b)*1024 + d*512 + J0 + row] = hn;
                if (rho == 256)   // final layer-1 hidden
                    out[(size_t)OUT_SEQ + ((size_t)((d*2+1)*64) + b)*512 + J0 + row] = hn;
            }
            __syncthreads();
        }
        gbar(d);   // h0n, h1 visible for next round
    }
}

extern "C" void kernel_launch(void* const* d_in, const int* in_sizes, int n_in,
                              void* d_out, int out_size) {
    const int*   tokens = (const int*)  d_in[0];
    const float* emb    = (const float*)d_in[1];
    const float* Wr     = (const float*)d_in[2];
    const float* Wz     = (const float*)d_in[3];
    const float* Ws     = (const float*)d_in[4];
    const float* br     = (const float*)d_in[5];
    const float* bz     = (const float*)d_in[6];
    const float* bs     = (const float*)d_in[7];
    float* out = (float*)d_out;

    cudaFuncSetAttribute(bigru_kernel,
                         cudaFuncAttributeMaxDynamicSharedMemorySize,
                         SMEM_FLOATS * sizeof(float));
    bigru_kernel<<<128, 512, SMEM_FLOATS * sizeof(float)>>>(
        tokens, emb, Wr, Wz, Ws, br, bz, bs, out);
}

// round 15
// speedup vs baseline: 1.9641x; 1.0517x over previous
#include <cuda_runtime.h>
#include <math.h>

#define SQ 256
#define NB 64
#define NH 512
#define OUT_SEQ (SQ*NB*2*NH)   // 16,777,216 floats of [S,B,2H]; hidd follows

typedef unsigned long long ull;

// ---------------- device scratch (no allocs allowed) ----------------
__device__ __align__(256) float dP[2u*3u*SQ*NH*NB];  // layer-0 x-proj + bias
__device__ __align__(256) float dHT0[2][2][NH*NB];   // layer-0 h, double buffered
__device__ __align__(256) float dHT1[2][NH*NB];      // layer-1 h
__device__ __align__(256) float dUT0[2][NH*NB];      // layer-0 u = r*h
__device__ __align__(256) float dUT1[2][NH*NB];      // layer-1 u
__device__ unsigned gBarCnt[2];
__device__ volatile unsigned gBarGen[2];

// Per-direction global barrier over 64 CTAs (sense-free generation counter).
// __threadfence() emits CCTL.IVALL on sm_103a -> post-barrier LDGs see other
// SMs' stores.
__device__ __forceinline__ void gbar(int d) {
    __syncthreads();
    if (threadIdx.x == 0) {
        __threadfence();
        unsigned gen = gBarGen[d];
        unsigned prev = atomicAdd(&gBarCnt[d], 1u);
        if (prev == 63u) {
            gBarCnt[d] = 0u;
            __threadfence();
            gBarGen[d] = gen + 1u;
        } else {
            while (gBarGen[d] == gen) { }
        }
        __threadfence();
    }
    __syncthreads();
}

__device__ __forceinline__ float sigf(float x) { return 1.0f / (1.0f + expf(-x)); }

// ---- packed fp32x2 helpers (FFMA2 via PTX: halves issue slots) ----
__device__ __forceinline__ void fma2(ull& c, ull a, ull b) {
    asm("fma.rn.f32x2 %0, %1, %2, %0;" : "+l"(c) : "l"(a), "l"(b));
}
__device__ __forceinline__ ull bcast2(float v) {
    ull r; asm("mov.b64 %0, {%1, %1};" : "=l"(r) : "f"(v)); return r;
}
__device__ __forceinline__ float2 unpk2(ull v) {
    float2 f; asm("mov.b64 {%0, %1}, %2;" : "=f"(f.x), "=f"(f.y) : "l"(v)); return f;
}

// ---------------- shared memory layout (floats) ----------------
//  proj overlay: As[16][132] at 0 (2112), Bs0 at 2112 (1088), Bs1 at 3200 (1088)
//  sRed stride 68: 272 B/row -> float4-aligned, bank-shifted.
//  sRed holds BOTH fused halves: rows [0,128) = L0, rows [128,256) = L1.
#define RSTR 68
#define OFF_WRZ0 0        // [k*16+row], k<512                              8192
#define OFF_WS0  8192     // [k*8+row],  k<512                              4096
#define OFF_WRZ1 12288    // [k*16+row], k<1024                            16384
#define OFF_WS1  28672    // [k*8+row],  k<1024                             8192
#define OFF_RED  36864    // 256 rows x 68                                 17408
#define OFF_Z0   54272
#define OFF_H0   54784
#define OFF_Z1   55296
#define OFF_H1   55808
#define SMEM_FLOATS 56320   // 225,280 bytes

// Fused-half 16-row GEMV: 256 threads, 8 K-splits x KPS.
// loc in [0,256): split=loc>>5, rows rg*4.., b = bg*8..
// k0 < 512 -> Xlo, else Xhi (pre-offset so X + k*64 is valid).
template<int KPS>
__device__ __forceinline__ void gemv16f(const float* __restrict__ Wt,
                                        const float* __restrict__ Xlo,
                                        const float* __restrict__ Xhi,
                                        float* __restrict__ sRed,
                                        int redBase, int loc)
{
    const int split = loc >> 5;        // 0..7
    const int rg = (loc >> 3) & 3;
    const int bg = loc & 7;
    const int k0 = split * KPS;
    const float* X = (k0 < 512) ? Xlo : Xhi;
    ull a[4][4];
    #pragma unroll
    for (int r = 0; r < 4; r++)
        #pragma unroll
        for (int q = 0; q < 4; q++) a[r][q] = 0ull;
    #pragma unroll 4
    for (int k = k0; k < k0 + KPS; k++) {
        const float4 w = *(const float4*)(Wt + k*16 + rg*4);
        const ull wp0 = bcast2(w.x), wp1 = bcast2(w.y),
                  wp2 = bcast2(w.z), wp3 = bcast2(w.w);
        const ulonglong2 xa = *(const ulonglong2*)(X + k*64 + bg*8);
        const ulonglong2 xb = *(const ulonglong2*)(X + k*64 + bg*8 + 4);
        fma2(a[0][0], wp0, xa.x); fma2(a[0][1], wp0, xa.y);
        fma2(a[0][2], wp0, xb.x); fma2(a[0][3], wp0, xb.y);
        fma2(a[1][0], wp1, xa.x); fma2(a[1][1], wp1, xa.y);
        fma2(a[1][2], wp1, xb.x); fma2(a[1][3], wp1, xb.y);
        fma2(a[2][0], wp2, xa.x); fma2(a[2][1], wp2, xa.y);
        fma2(a[2][2], wp2, xb.x); fma2(a[2][3], wp2, xb.y);
        fma2(a[3][0], wp3, xa.x); fma2(a[3][1], wp3, xa.y);
        fma2(a[3][2], wp3, xb.x); fma2(a[3][3], wp3, xb.y);
    }
    #pragma unroll
    for (int r = 0; r < 4; r++) {
        float* pr = sRed + (size_t)(redBase + split*16 + rg*4 + r)*RSTR + bg*8;
        *(ulonglong2*)(pr)     = make_ulonglong2(a[r][0], a[r][1]);
        *(ulonglong2*)(pr + 4) = make_ulonglong2(a[r][2], a[r][3]);
    }
}

// Fused-half 8-row GEMV: 256 threads, 16 K-splits x KPS.
template<int KPS>
__device__ __forceinline__ void gemv8f(const float* __restrict__ Wt,
                                       const float* __restrict__ Xlo,
                                       const float* __restrict__ Xhi,
                                       float* __restrict__ sRed,
                                       int redBase, int loc)
{
    const int split = loc >> 4;        // 0..15
    const int rg = (loc >> 3) & 1;
    const int bg = loc & 7;
    const int k0 = split * KPS;
    const float* X = (k0 < 512) ? Xlo : Xhi;
    ull a[4][4];
    #pragma unroll
    for (int r = 0; r < 4; r++)
        #pragma unroll
        for (int q = 0; q < 4; q++) a[r][q] = 0ull;
    #pragma unroll 4
    for (int k = k0; k < k0 + KPS; k++) {
        const float4 w = *(const float4*)(Wt + k*8 + rg*4);
        const ull wp0 = bcast2(w.x), wp1 = bcast2(w.y),
                  wp2 = bcast2(w.z), wp3 = bcast2(w.w);
        const ulonglong2 xa = *(const ulonglong2*)(X + k*64 + bg*8);
        const ulonglong2 xb = *(const ulonglong2*)(X + k*64 + bg*8 + 4);
        fma2(a[0][0], wp0, xa.x); fma2(a[0][1], wp0, xa.y);
        fma2(a[0][2], wp0, xb.x); fma2(a[0][3], wp0, xb.y);
        fma2(a[1][0], wp1, xa.x); fma2(a[1][1], wp1, xa.y);
        fma2(a[1][2], wp1, xb.x); fma2(a[1][3], wp1, xb.y);
        fma2(a[2][0], wp2, xa.x); fma2(a[2][1], wp2, xa.y);
        fma2(a[2][2], wp2, xb.x); fma2(a[2][3], wp2, xb.y);
        fma2(a[3][0], wp3, xa.x); fma2(a[3][1], wp3, xa.y);
        fma2(a[3][2], wp3, xb.x); fma2(a[3][3], wp3, xb.y);
    }
    #pragma unroll
    for (int r = 0; r < 4; r++) {
        float* pr = sRed + (size_t)(redBase + split*8 + rg*4 + r)*RSTR + bg*8;
        *(ulonglong2*)(pr)     = make_ulonglong2(a[r][0], a[r][1]);
        *(ulonglong2*)(pr + 4) = make_ulonglong2(a[r][2], a[r][3]);
    }
}

__global__ void __launch_bounds__(512, 1)
bigru_kernel(const int*   __restrict__ tokens,
             const float* __restrict__ emb,
             const float* __restrict__ Wr,
             const float* __restrict__ Wz,
             const float* __restrict__ Ws,
             const float* __restrict__ br,
             const float* __restrict__ bz,
             const float* __restrict__ bs,
             float*       __restrict__ out)
{
    extern __shared__ float smem[];
    __shared__ int sTok[128];

    const int tid = threadIdx.x;
    const int d   = blockIdx.x >> 6;   // direction 0/1
    const int c   = blockIdx.x & 63;   // cta within direction
    const int J0  = c * 8;             // owned hidden-unit slice (both layers)

    float* P   = dP + (size_t)d * 3u * SQ * NH * NB;
    float* HT1 = dHT1[d];
    float* UT0 = dUT0[d];
    float* UT1 = dUT1[d];

    const int wlo0 = (d*2 + 0) * 512;
    const int wlo1 = (d*2 + 1) * 512;

    float* As   = smem;
    float* sRed = smem + OFF_RED;
    float* sZ0  = smem + OFF_Z0;
    float* sH0  = smem + OFF_H0;
    float* sZ1  = smem + OFF_Z1;
    float* sH1  = smem + OFF_H1;

    // zero own h slices (h0 = h1 = 0); published by the proj-end gbar
    if (tid < 512) {
        dHT0[d][0][J0*64 + tid] = 0.0f;
        dHT0[d][1][J0*64 + tid] = 0.0f;
        HT1[J0*64 + tid] = 0.0f;
    }

    // ------------- layer-0 input projections: P[gate][t][j][b] -------------
    // t-paired double-tiles: both 256-thread halves share one As weight tile,
    // each computes a different t. 3 gates x 4 jt x 128 t-pairs = 1536; 24/CTA.
    {
        const int half = tid >> 8;          // 0/1 -> t = 2u+half
        const int htid = tid & 255;
        float* Bs = smem + 2112 + half*1088;
        const int ty = htid >> 4, tx = htid & 15;

        for (int tb = 0; tb < 24; tb++) {
            const int tile = c * 24 + tb;
            const int up   = tile & 127;
            const int grp  = tile >> 7;     // 0..11
            const int gate = grp >> 2;
            const int jt   = grp & 3;
            const int t    = up*2 + half;
            const float* W = (gate == 0) ? Wr : (gate == 1) ? Wz : Ws;
            const float* Wbase = W + (size_t)(wlo0 + jt*128) * 1024;

            if (htid < 64) {
                const int tp = d ? (255 - t) : t;
                sTok[half*64 + htid] = tokens[tp*64 + htid];
            }

            ull acc[4][4];   // [row-pair][b]
            #pragma unroll
            for (int rp = 0; rp < 4; rp++)
                #pragma unroll
                for (int b = 0; b < 4; b++) acc[rp][b] = 0ull;

            for (int kc = 0; kc < 512; kc += 16) {
                __syncthreads();
                {   // As: all 512 threads, one float4 each (128j x 16k)
                    const int j = tid >> 2, kq = tid & 3;
                    const float4 v = *(const float4*)(Wbase + (size_t)j*1024 + kc + kq*4);
                    As[(kq*4+0)*132 + j] = v.x;
                    As[(kq*4+1)*132 + j] = v.y;
                    As[(kq*4+2)*132 + j] = v.z;
                    As[(kq*4+3)*132 + j] = v.w;
                }
                {   // Bs: per half (16k x 64b)
                    const int b = htid >> 2, kq = htid & 3;
                    const float4 v = *(const float4*)(emb + (size_t)sTok[half*64+b]*512 + kc + kq*4);
                    Bs[(kq*4+0)*68 + b] = v.x;
                    Bs[(kq*4+1)*68 + b] = v.y;
                    Bs[(kq*4+2)*68 + b] = v.z;
                    Bs[(kq*4+3)*68 + b] = v.w;
                }
                __syncthreads();
                #pragma unroll
                for (int k = 0; k < 16; k++) {
                    const ulonglong2 a01 = *(const ulonglong2*)(As + k*132 + ty*8);
                    const ulonglong2 a23 = *(const ulonglong2*)(As + k*132 + ty*8 + 4);
                    const float4 bq = *(const float4*)(Bs + k*68 + tx*4);
                    const ull b0 = bcast2(bq.x), b1 = bcast2(bq.y),
                              b2 = bcast2(bq.z), b3 = bcast2(bq.w);
                    fma2(acc[0][0], a01.x, b0); fma2(acc[0][1], a01.x, b1);
                    fma2(acc[0][2], a01.x, b2); fma2(acc[0][3], a01.x, b3);
                    fma2(acc[1][0], a01.y, b0); fma2(acc[1][1], a01.y, b1);
                    fma2(acc[1][2], a01.y, b2); fma2(acc[1][3], a01.y, b3);
                    fma2(acc[2][0], a23.x, b0); fma2(acc[2][1], a23.x, b1);
                    fma2(acc[2][2], a23.x, b2); fma2(acc[2][3], a23.x, b3);
                    fma2(acc[3][0], a23.y, b0); fma2(acc[3][1], a23.y, b1);
                    fma2(acc[3][2], a23.y, b2); fma2(acc[3][3], a23.y, b3);
                }
            }
            const float* bias = ((gate==0) ? br : (gate==1) ? bz : bs) + wlo0 + jt*128 + ty*8;
            float* Pout = P + (((size_t)gate*256 + t)*512 + jt*128 + ty*8)*64 + tx*4;
            #pragma unroll
            for (int rp = 0; rp < 4; rp++) {
                const float2 u0 = unpk2(acc[rp][0]);
                const float2 u1 = unpk2(acc[rp][1]);
                const float2 u2 = unpk2(acc[rp][2]);
                const float2 u3 = unpk2(acc[rp][3]);
                const float be = bias[rp*2], bo = bias[rp*2+1];
                float4 oe = make_float4(u0.x + be, u1.x + be, u2.x + be, u3.x + be);
                float4 oo = make_float4(u0.y + bo, u1.y + bo, u2.y + bo, u3.y + bo);
                *(float4*)(Pout + (size_t)(rp*2    )*64) = oe;
                *(float4*)(Pout + (size_t)(rp*2 + 1)*64) = oo;
            }
        }
    }
    __syncthreads();

    // ------------- stage recurrence weights (coalesced LDG) -------------
    for (int idx = tid; idx < 8192; idx += 512) {     // WRZ0: h-part K=512
        const int row = idx >> 9, k = idx & 511;
        const float* W = (row < 8) ? Wr : Wz;
        smem[OFF_WRZ0 + k*16 + row] = W[(size_t)(wlo0 + J0 + (row & 7))*1024 + 512 + k];
    }
    for (int idx = tid; idx < 4096; idx += 512) {     // WS0: h-part K=512
        const int row = idx >> 9, k = idx & 511;
        smem[OFF_WS0 + k*8 + row] = Ws[(size_t)(wlo0 + J0 + row)*1024 + 512 + k];
    }
    for (int idx = tid; idx < 16384; idx += 512) {    // WRZ1: full K=1024
        const int row = idx >> 10, k = idx & 1023;
        const float* W = (row < 8) ? Wr : Wz;
        smem[OFF_WRZ1 + k*16 + row] = W[(size_t)(wlo1 + J0 + (row & 7))*1024 + k];
    }
    for (int idx = tid; idx < 8192; idx += 512) {     // WS1: full K=1024
        const int row = idx >> 10, k = idx & 1023;
        smem[OFF_WS1 + k*8 + row] = Ws[(size_t)(wlo1 + J0 + row)*1024 + k];
    }
    gbar(d);   // P + h zeros visible everywhere

    // ------------- pipelined recurrence: layer0 @ t=rho, layer1 @ t=rho-1 ----
    // Per round only TWO fused phases:
    //   A: rz0 (thr 0-255) + rz1 (thr 256-511) -> fused reduce -> gbar
    //   B: s0  (thr 0-255) + s1  (thr 256-511) -> fused reduce -> gbar
    for (int rho = 0; rho < 257; rho++) {
        const int cur = rho & 1;
        float* HT0c = dHT0[d][cur];       // h0 after t=rho-1 (== y0 for layer1)
        float* HT0n = dHT0[d][cur ^ 1];   // h0 write target
        const bool L0 = (rho < 256);
        const bool L1 = (rho >= 1);
        const int t0 = rho, t1 = rho - 1;

        // ---- Phase A: fused rz GEMVs ----
        if (L0 && tid < 256)
            gemv16f<64>(smem + OFF_WRZ0, HT0c, HT0c, sRed, 0, tid);
        if (L1 && tid >= 256)
            gemv16f<128>(smem + OFF_WRZ1, HT0c, HT1 - 512*64, sRed, 128, tid - 256);
        __syncthreads();
        {   // fused rz reduce: 32 rows x 64 b, float4 per thread
            const int row = tid >> 4;          // 0..31
            const int b4  = (tid & 15) * 4;
            if (row < 16) {
                if (L0) {
                    float4 s = make_float4(0.f,0.f,0.f,0.f);
                    #pragma unroll
                    for (int sp = 0; sp < 8; sp++) {
                        const float4 v = *(const float4*)(sRed + (sp*16 + row)*RSTR + b4);
                        s.x += v.x; s.y += v.y; s.z += v.z; s.w += v.w;
                    }
                    const int gate = row >> 3, j = row & 7;
                    const float4 pre = *(const float4*)(P + (((size_t)gate*256 + t0)*512 + J0 + j)*64 + b4);
                    float4 g;
                    g.x = sigf(pre.x + s.x); g.y = sigf(pre.y + s.y);
                    g.z = sigf(pre.z + s.z); g.w = sigf(pre.w + s.w);
                    if (gate == 0) {
                        const float4 h = *(const float4*)(HT0c + (J0 + j)*64 + b4);
                        *(float4*)(sH0 + j*64 + b4) = h;
                        float4 u; u.x=g.x*h.x; u.y=g.y*h.y; u.z=g.z*h.z; u.w=g.w*h.w;
                        *(float4*)(UT0 + (J0 + j)*64 + b4) = u;
                    } else {
                        *(float4*)(sZ0 + j*64 + b4) = g;
                    }
                }
            } else {
                if (L1) {
                    const int rowl = row - 16;
                    float4 s = make_float4(0.f,0.f,0.f,0.f);
                    #pragma unroll
                    for (int sp = 0; sp < 8; sp++) {
                        const float4 v = *(const float4*)(sRed + (128 + sp*16 + rowl)*RSTR + b4);
                        s.x += v.x; s.y += v.y; s.z += v.z; s.w += v.w;
                    }
                    const int gate = rowl >> 3, j = rowl & 7;
                    const float bb = ((gate == 0) ? br : bz)[wlo1 + J0 + j];
                    float4 g;
                    g.x = sigf(bb + s.x); g.y = sigf(bb + s.y);
                    g.z = sigf(bb + s.z); g.w = sigf(bb + s.w);
                    if (gate == 0) {
                        const float4 h = *(const float4*)(HT1 + (J0 + j)*64 + b4);
                        *(float4*)(sH1 + j*64 + b4) = h;
                        float4 u; u.x=g.x*h.x; u.y=g.y*h.y; u.z=g.z*h.z; u.w=g.w*h.w;
                        *(float4*)(UT1 + (J0 + j)*64 + b4) = u;
                    } else {
                        *(float4*)(sZ1 + j*64 + b4) = g;
                    }
                }
            }
        }
        gbar(d);   // u0, u1 visible to all CTAs

        // ---- Phase B: fused s GEMVs ----
        if (L0 && tid < 256)
            gemv8f<32>(smem + OFF_WS0, UT0, UT0, sRed, 0, tid);
        if (L1 && tid >= 256)
            gemv8f<64>(smem + OFF_WS1, HT0c, UT1 - 512*64, sRed, 128, tid - 256);
        __syncthreads();
        {   // fused s reduce: 16 rows x 64 b, float2 per thread
            const int row = tid >> 5;          // 0..15
            const int b2  = (tid & 31) * 2;
            if (row < 8) {
                if (L0) {
                    float sx = 0.f, sy = 0.f;
                    #pragma unroll
                    for (int sp = 0; sp < 16; sp++) {
                        const float2 v = *(const float2*)(sRed + (sp*8 + row)*RSTR + b2);
                        sx += v.x; sy += v.y;
                    }
                    const float2 pre = *(const float2*)(P + (((size_t)2*256 + t0)*512 + J0 + row)*64 + b2);
                    const float ssx = tanhf(pre.x + sx);
                    const float ssy = tanhf(pre.y + sy);
                    const float2 z = *(const float2*)(sZ0 + row*64 + b2);
                    const float2 h = *(const float2*)(sH0 + row*64 + b2);
                    const float hnx = z.x*h.x + (1.f - z.x)*ssx;
                    const float hny = z.y*h.y + (1.f - z.y)*ssy;
                    *(float2*)(HT0n + (J0 + row)*64 + b2) = make_float2(hnx, hny);
                    if (rho == 255) {   // final layer-0 hidden
                        out[(size_t)OUT_SEQ + ((size_t)((d*2+0)*64) + b2    )*512 + J0 + row] = hnx;
                        out[(size_t)OUT_SEQ + ((size_t)((d*2+0)*64) + b2 + 1)*512 + J0 + row] = hny;
                    }
                }
            } else {
                if (L1) {
                    const int rowl = row - 8;
                    float sx = 0.f, sy = 0.f;
                    #pragma unroll
                    for (int sp = 0; sp < 16; sp++) {
                        const float2 v = *(const float2*)(sRed + (128 + sp*8 + rowl)*RSTR + b2);
                        sx += v.x; sy += v.y;
                    }
                    const float bb = bs[wlo1 + J0 + rowl];
                    const float ssx = tanhf(bb + sx);
                    const float ssy = tanhf(bb + sy);
                    const float2 z = *(const float2*)(sZ1 + rowl*64 + b2);
                    const float2 h = *(const float2*)(sH1 + rowl*64 + b2);
                    const float hnx = z.x*h.x + (1.f - z.x)*ssx;
                    const float hny = z.y*h.y + (1.f - z.y)*ssy;
                    *(float2*)(HT1 + (J0 + rowl)*64 + b2) = make_float2(hnx, hny);
                    out[((size_t)t1*64 + b2    )*1024 + d*512 + J0 + rowl] = hnx;
                    out[((size_t)t1*64 + b2 + 1)*1024 + d*512 + J0 + rowl] = hny;
                    if (rho == 256) {   // final layer-1 hidden
                        out[(size_t)OUT_SEQ + ((size_t)((d*2+1)*64) + b2    )*512 + J0 + rowl] = hnx;
                        out[(size_t)OUT_SEQ + ((size_t)((d*2+1)*64) + b2 + 1)*512 + J0 + rowl] = hny;
                    }
                }
            }
        }
        gbar(d);   // h0n, h1 visible for next round
    }
}

extern "C" void kernel_launch(void* const* d_in, const int* in_sizes, int n_in,
                              void* d_out, int out_size) {
    const int*   tokens = (const int*)  d_in[0];
    const float* emb    = (const float*)d_in[1];
    const float* Wr     = (const float*)d_in[2];
    const float* Wz     = (const float*)d_in[3];
    const float* Ws     = (const float*)d_in[4];
    const float* br     = (const float*)d_in[5];
    const float* bz     = (const float*)d_in[6];
    const float* bs     = (const float*)d_in[7];
    float* out = (float*)d_out;

    cudaFuncSetAttribute(bigru_kernel,
                         cudaFuncAttributeMaxDynamicSharedMemorySize,
                         SMEM_FLOATS * sizeof(float));
    bigru_kernel<<<128, 512, SMEM_FLOATS * sizeof(float)>>>(
        tokens, emb, Wr, Wz, Ws, br, bz, bs, out);
}

// round 16
// speedup vs baseline: 2.1264x; 1.0826x over previous
#include <cuda_runtime.h>
#include <math.h>

#define SQ 256
#define NB 64
#define NH 512
#define OUT_SEQ (SQ*NB*2*NH)   // 16,777,216 floats of [S,B,2H]; hidd follows

typedef unsigned long long ull;

// ---------------- device scratch (no allocs allowed) ----------------
__device__ __align__(256) float dP[2u*3u*SQ*NH*NB];  // layer-0 x-proj + bias
__device__ __align__(256) float dHT0[2][2][NH*NB];   // layer-0 h, double buffered
__device__ __align__(256) float dHT1[2][NH*NB];      // layer-1 h
__device__ __align__(256) float dUT0[2][NH*NB];      // layer-0 u = r*h
__device__ __align__(256) float dUT1[2][NH*NB];      // layer-1 u
__device__ unsigned gBarCnt[2];
__device__ volatile unsigned gBarGen[2];

// Per-direction global barrier over 64 CTAs (sense-free generation counter).
// __threadfence() emits CCTL.IVALL on sm_103a -> post-barrier LDGs see other
// SMs' stores.
__device__ __forceinline__ void gbar(int d) {
    __syncthreads();
    if (threadIdx.x == 0) {
        __threadfence();
        unsigned gen = gBarGen[d];
        unsigned prev = atomicAdd(&gBarCnt[d], 1u);
        if (prev == 63u) {
            gBarCnt[d] = 0u;
            __threadfence();
            gBarGen[d] = gen + 1u;
        } else {
            while (gBarGen[d] == gen) { }
        }
        __threadfence();
    }
    __syncthreads();
}

__device__ __forceinline__ float sigf(float x) { return 1.0f / (1.0f + expf(-x)); }

// ---- packed fp32x2 helpers (FFMA2 via PTX: halves issue slots) ----
__device__ __forceinline__ void fma2(ull& c, ull a, ull b) {
    asm("fma.rn.f32x2 %0, %1, %2, %0;" : "+l"(c) : "l"(a), "l"(b));
}
__device__ __forceinline__ ull bcast2(float v) {
    ull r; asm("mov.b64 %0, {%1, %1};" : "=l"(r) : "f"(v)); return r;
}
__device__ __forceinline__ float2 unpk2(ull v) {
    float2 f; asm("mov.b64 {%0, %1}, %2;" : "=f"(f.x), "=f"(f.y) : "l"(v)); return f;
}

// ---------------- shared memory layout (floats) ----------------
//  proj overlay: As[16][132] at 0 (2112), Bs0 at 2112 (1088), Bs1 at 3200 (1088)
//  sRed stride 68: 272 B/row -> float4-aligned, bank-shifted.
//  Phase A sRed rows: [0,64)=rz0, [64,192)=rz1, [192,256)=s1x
//  Phase B sRed rows: [0,128)=s0, [128,256)=s1h
#define RSTR 68
#define OFF_WRZ0 0        // [k*16+row], k<512                              8192
#define OFF_WS0  8192     // [k*8+row],  k<512                              4096
#define OFF_WRZ1 12288    // [k*16+row], k<1024                            16384
#define OFF_WS1  28672    // [k*8+row],  k<1024 (x-part k<512, h-part k>=512) 8192
#define OFF_RED  36864    // 256 rows x 68                                 17408
#define OFF_Z0   54272
#define OFF_H0   54784
#define OFF_Z1   55296
#define OFF_H1   55808
#define OFF_S1X  56320    // s1 x-part partial: 8 rows x 64 b                512
#define SMEM_FLOATS 56832   // 227,328 bytes

// Generic 16-row GEMV: NSPLIT K-splits x KPS, loc in [0, NSPLIT*32).
// k0 < 512 -> Xlo, else Xhi (pre-offset so X + k*64 is valid).
template<int NSPLIT, int KPS>
__device__ __forceinline__ void gemv16g(const float* __restrict__ Wt,
                                        const float* __restrict__ Xlo,
                                        const float* __restrict__ Xhi,
                                        float* __restrict__ sRed,
                                        int redBase, int loc)
{
    const int split = loc >> 5;        // 0..NSPLIT-1
    const int rg = (loc >> 3) & 3;
    const int bg = loc & 7;
    const int k0 = split * KPS;
    const float* X = (k0 < 512) ? Xlo : Xhi;
    ull a[4][4];
    #pragma unroll
    for (int r = 0; r < 4; r++)
        #pragma unroll
        for (int q = 0; q < 4; q++) a[r][q] = 0ull;
    #pragma unroll 4
    for (int k = k0; k < k0 + KPS; k++) {
        const float4 w = *(const float4*)(Wt + k*16 + rg*4);
        const ull wp0 = bcast2(w.x), wp1 = bcast2(w.y),
                  wp2 = bcast2(w.z), wp3 = bcast2(w.w);
        const ulonglong2 xa = *(const ulonglong2*)(X + k*64 + bg*8);
        const ulonglong2 xb = *(const ulonglong2*)(X + k*64 + bg*8 + 4);
        fma2(a[0][0], wp0, xa.x); fma2(a[0][1], wp0, xa.y);
        fma2(a[0][2], wp0, xb.x); fma2(a[0][3], wp0, xb.y);
        fma2(a[1][0], wp1, xa.x); fma2(a[1][1], wp1, xa.y);
        fma2(a[1][2], wp1, xb.x); fma2(a[1][3], wp1, xb.y);
        fma2(a[2][0], wp2, xa.x); fma2(a[2][1], wp2, xa.y);
        fma2(a[2][2], wp2, xb.x); fma2(a[2][3], wp2, xb.y);
        fma2(a[3][0], wp3, xa.x); fma2(a[3][1], wp3, xa.y);
        fma2(a[3][2], wp3, xb.x); fma2(a[3][3], wp3, xb.y);
    }
    #pragma unroll
    for (int r = 0; r < 4; r++) {
        float* pr = sRed + (size_t)(redBase + split*16 + rg*4 + r)*RSTR + bg*8;
        *(ulonglong2*)(pr)     = make_ulonglong2(a[r][0], a[r][1]);
        *(ulonglong2*)(pr + 4) = make_ulonglong2(a[r][2], a[r][3]);
    }
}

// Generic 8-row GEMV: NSPLIT K-splits x KPS, loc in [0, NSPLIT*16).
template<int NSPLIT, int KPS>
__device__ __forceinline__ void gemv8g(const float* __restrict__ Wt,
                                       const float* __restrict__ Xlo,
                                       const float* __restrict__ Xhi,
                                       float* __restrict__ sRed,
                                       int redBase, int loc)
{
    const int split = loc >> 4;        // 0..NSPLIT-1
    const int rg = (loc >> 3) & 1;
    const int bg = loc & 7;
    const int k0 = split * KPS;
    const float* X = (k0 < 512) ? Xlo : Xhi;
    ull a[4][4];
    #pragma unroll
    for (int r = 0; r < 4; r++)
        #pragma unroll
        for (int q = 0; q < 4; q++) a[r][q] = 0ull;
    #pragma unroll 8
    for (int k = k0; k < k0 + KPS; k++) {
        const float4 w = *(const float4*)(Wt + k*8 + rg*4);
        const ull wp0 = bcast2(w.x), wp1 = bcast2(w.y),
                  wp2 = bcast2(w.z), wp3 = bcast2(w.w);
        const ulonglong2 xa = *(const ulonglong2*)(X + k*64 + bg*8);
        const ulonglong2 xb = *(const ulonglong2*)(X + k*64 + bg*8 + 4);
        fma2(a[0][0], wp0, xa.x); fma2(a[0][1], wp0, xa.y);
        fma2(a[0][2], wp0, xb.x); fma2(a[0][3], wp0, xb.y);
        fma2(a[1][0], wp1, xa.x); fma2(a[1][1], wp1, xa.y);
        fma2(a[1][2], wp1, xb.x); fma2(a[1][3], wp1, xb.y);
        fma2(a[2][0], wp2, xa.x); fma2(a[2][1], wp2, xa.y);
        fma2(a[2][2], wp2, xb.x); fma2(a[2][3], wp2, xb.y);
        fma2(a[3][0], wp3, xa.x); fma2(a[3][1], wp3, xa.y);
        fma2(a[3][2], wp3, xb.x); fma2(a[3][3], wp3, xb.y);
    }
    #pragma unroll
    for (int r = 0; r < 4; r++) {
        float* pr = sRed + (size_t)(redBase + split*8 + rg*4 + r)*RSTR + bg*8;
        *(ulonglong2*)(pr)     = make_ulonglong2(a[r][0], a[r][1]);
        *(ulonglong2*)(pr + 4) = make_ulonglong2(a[r][2], a[r][3]);
    }
}

__global__ void __launch_bounds__(512, 1)
bigru_kernel(const int*   __restrict__ tokens,
             const float* __restrict__ emb,
             const float* __restrict__ Wr,
             const float* __restrict__ Wz,
             const float* __restrict__ Ws,
             const float* __restrict__ br,
             const float* __restrict__ bz,
             const float* __restrict__ bs,
             float*       __restrict__ out)
{
    extern __shared__ float smem[];
    __shared__ int sTok[128];

    const int tid = threadIdx.x;
    const int d   = blockIdx.x >> 6;   // direction 0/1
    const int c   = blockIdx.x & 63;   // cta within direction
    const int J0  = c * 8;             // owned hidden-unit slice (both layers)

    float* P   = dP + (size_t)d * 3u * SQ * NH * NB;
    float* HT1 = dHT1[d];
    float* UT0 = dUT0[d];
    float* UT1 = dUT1[d];

    const int wlo0 = (d*2 + 0) * 512;
    const int wlo1 = (d*2 + 1) * 512;

    float* As   = smem;
    float* sRed = smem + OFF_RED;
    float* sZ0  = smem + OFF_Z0;
    float* sH0  = smem + OFF_H0;
    float* sZ1  = smem + OFF_Z1;
    float* sH1  = smem + OFF_H1;
    float* sS1X = smem + OFF_S1X;

    // zero own h slices (h0 = h1 = 0); published by the proj-end gbar
    if (tid < 512) {
        dHT0[d][0][J0*64 + tid] = 0.0f;
        dHT0[d][1][J0*64 + tid] = 0.0f;
        HT1[J0*64 + tid] = 0.0f;
    }

    // ------------- layer-0 input projections: P[gate][t][j][b] -------------
    // t-paired double-tiles: both 256-thread halves share one As weight tile,
    // each computes a different t. 3 gates x 4 jt x 128 t-pairs = 1536; 24/CTA.
    {
        const int half = tid >> 8;          // 0/1 -> t = 2u+half
        const int htid = tid & 255;
        float* Bs = smem + 2112 + half*1088;
        const int ty = htid >> 4, tx = htid & 15;

        for (int tb = 0; tb < 24; tb++) {
            const int tile = c * 24 + tb;
            const int up   = tile & 127;
            const int grp  = tile >> 7;     // 0..11
            const int gate = grp >> 2;
            const int jt   = grp & 3;
            const int t    = up*2 + half;
            const float* W = (gate == 0) ? Wr : (gate == 1) ? Wz : Ws;
            const float* Wbase = W + (size_t)(wlo0 + jt*128) * 1024;

            if (htid < 64) {
                const int tp = d ? (255 - t) : t;
                sTok[half*64 + htid] = tokens[tp*64 + htid];
            }

            ull acc[4][4];   // [row-pair][b]
            #pragma unroll
            for (int rp = 0; rp < 4; rp++)
                #pragma unroll
                for (int b = 0; b < 4; b++) acc[rp][b] = 0ull;

            for (int kc = 0; kc < 512; kc += 16) {
                __syncthreads();
                {   // As: all 512 threads, one float4 each (128j x 16k)
                    const int j = tid >> 2, kq = tid & 3;
                    const float4 v = *(const float4*)(Wbase + (size_t)j*1024 + kc + kq*4);
                    As[(kq*4+0)*132 + j] = v.x;
                    As[(kq*4+1)*132 + j] = v.y;
                    As[(kq*4+2)*132 + j] = v.z;
                    As[(kq*4+3)*132 + j] = v.w;
                }
                {   // Bs: per half (16k x 64b)
                    const int b = htid >> 2, kq = htid & 3;
                    const float4 v = *(const float4*)(emb + (size_t)sTok[half*64+b]*512 + kc + kq*4);
                    Bs[(kq*4+0)*68 + b] = v.x;
                    Bs[(kq*4+1)*68 + b] = v.y;
                    Bs[(kq*4+2)*68 + b] = v.z;
                    Bs[(kq*4+3)*68 + b] = v.w;
                }
                __syncthreads();
                #pragma unroll
                for (int k = 0; k < 16; k++) {
                    const ulonglong2 a01 = *(const ulonglong2*)(As + k*132 + ty*8);
                    const ulonglong2 a23 = *(const ulonglong2*)(As + k*132 + ty*8 + 4);
                    const float4 bq = *(const float4*)(Bs + k*68 + tx*4);
                    const ull b0 = bcast2(bq.x), b1 = bcast2(bq.y),
                              b2 = bcast2(bq.z), b3 = bcast2(bq.w);
                    fma2(acc[0][0], a01.x, b0); fma2(acc[0][1], a01.x, b1);
                    fma2(acc[0][2], a01.x, b2); fma2(acc[0][3], a01.x, b3);
                    fma2(acc[1][0], a01.y, b0); fma2(acc[1][1], a01.y, b1);
                    fma2(acc[1][2], a01.y, b2); fma2(acc[1][3], a01.y, b3);
                    fma2(acc[2][0], a23.x, b0); fma2(acc[2][1], a23.x, b1);
                    fma2(acc[2][2], a23.x, b2); fma2(acc[2][3], a23.x, b3);
                    fma2(acc[3][0], a23.y, b0); fma2(acc[3][1], a23.y, b1);
                    fma2(acc[3][2], a23.y, b2); fma2(acc[3][3], a23.y, b3);
                }
            }
            const float* bias = ((gate==0) ? br : (gate==1) ? bz : bs) + wlo0 + jt*128 + ty*8;
            float* Pout = P + (((size_t)gate*256 + t)*512 + jt*128 + ty*8)*64 + tx*4;
            #pragma unroll
            for (int rp = 0; rp < 4; rp++) {
                const float2 u0 = unpk2(acc[rp][0]);
                const float2 u1 = unpk2(acc[rp][1]);
                const float2 u2 = unpk2(acc[rp][2]);
                const float2 u3 = unpk2(acc[rp][3]);
                const float be = bias[rp*2], bo = bias[rp*2+1];
                float4 oe = make_float4(u0.x + be, u1.x + be, u2.x + be, u3.x + be);
                float4 oo = make_float4(u0.y + bo, u1.y + bo, u2.y + bo, u3.y + bo);
                *(float4*)(Pout + (size_t)(rp*2    )*64) = oe;
                *(float4*)(Pout + (size_t)(rp*2 + 1)*64) = oo;
            }
        }
    }
    __syncthreads();

    // ------------- stage recurrence weights (coalesced LDG) -------------
    for (int idx = tid; idx < 8192; idx += 512) {     // WRZ0: h-part K=512
        const int row = idx >> 9, k = idx & 511;
        const float* W = (row < 8) ? Wr : Wz;
        smem[OFF_WRZ0 + k*16 + row] = W[(size_t)(wlo0 + J0 + (row & 7))*1024 + 512 + k];
    }
    for (int idx = tid; idx < 4096; idx += 512) {     // WS0: h-part K=512
        const int row = idx >> 9, k = idx & 511;
        smem[OFF_WS0 + k*8 + row] = Ws[(size_t)(wlo0 + J0 + row)*1024 + 512 + k];
    }
    for (int idx = tid; idx < 16384; idx += 512) {    // WRZ1: full K=1024
        const int row = idx >> 10, k = idx & 1023;
        const float* W = (row < 8) ? Wr : Wz;
        smem[OFF_WRZ1 + k*16 + row] = W[(size_t)(wlo1 + J0 + (row & 7))*1024 + k];
    }
    for (int idx = tid; idx < 8192; idx += 512) {     // WS1: full K=1024
        const int row = idx >> 10, k = idx & 1023;
        smem[OFF_WS1 + k*8 + row] = Ws[(size_t)(wlo1 + J0 + row)*1024 + k];
    }
    gbar(d);   // P + h zeros visible everywhere

    // ------------- pipelined recurrence: layer0 @ t=rho, layer1 @ t=rho-1 ----
    // Phase A: rz0 (128 thr, KPS128) + rz1 (256 thr, KPS128) + s1x (128 thr,
    //          KPS64, vs L1-hot HT0c) -> fused reduce -> gbar
    // Phase B: s0 (256 thr, KPS32) + s1h (256 thr, KPS32, vs UT1) -> reduce -> gbar
    for (int rho = 0; rho < 257; rho++) {
        const int cur = rho & 1;
        float* HT0c = dHT0[d][cur];       // h0 after t=rho-1 (== y0 for layer1)
        float* HT0n = dHT0[d][cur ^ 1];   // h0 write target
        const bool L0 = (rho < 256);
        const bool L1 = (rho >= 1);
        const int t0 = rho, t1 = rho - 1;

        // ---- Phase A ----
        if (L0 && tid < 128)
            gemv16g<4,128>(smem + OFF_WRZ0, HT0c, HT0c, sRed, 0, tid);
        if (L1 && tid >= 128 && tid < 384)
            gemv16g<8,128>(smem + OFF_WRZ1, HT0c, HT1 - 512*64, sRed, 64, tid - 128);
        if (L1 && tid >= 384)
            gemv8g<8,64>(smem + OFF_WS1, HT0c, HT0c, sRed, 192, tid - 384);
        __syncthreads();
        {   // fused rz reduce: 32 rows x 64 b, float4 per thread
            const int row = tid >> 4;          // 0..31
            const int b4  = (tid & 15) * 4;
            if (row < 16) {
                if (L0) {
                    float4 s = make_float4(0.f,0.f,0.f,0.f);
                    #pragma unroll
                    for (int sp = 0; sp < 4; sp++) {
                        const float4 v = *(const float4*)(sRed + (sp*16 + row)*RSTR + b4);
                        s.x += v.x; s.y += v.y; s.z += v.z; s.w += v.w;
                    }
                    const int gate = row >> 3, j = row & 7;
                    const float4 pre = *(const float4*)(P + (((size_t)gate*256 + t0)*512 + J0 + j)*64 + b4);
                    float4 g;
                    g.x = sigf(pre.x + s.x); g.y = sigf(pre.y + s.y);
                    g.z = sigf(pre.z + s.z); g.w = sigf(pre.w + s.w);
                    if (gate == 0) {
                        const float4 h = *(const float4*)(HT0c + (J0 + j)*64 + b4);
                        *(float4*)(sH0 + j*64 + b4) = h;
                        float4 u; u.x=g.x*h.x; u.y=g.y*h.y; u.z=g.z*h.z; u.w=g.w*h.w;
                        *(float4*)(UT0 + (J0 + j)*64 + b4) = u;
                    } else {
                        *(float4*)(sZ0 + j*64 + b4) = g;
                    }
                }
            } else {
                if (L1) {
                    const int rowl = row - 16;
                    float4 s = make_float4(0.f,0.f,0.f,0.f);
                    #pragma unroll
                    for (int sp = 0; sp < 8; sp++) {
                        const float4 v = *(const float4*)(sRed + (64 + sp*16 + rowl)*RSTR + b4);
                        s.x += v.x; s.y += v.y; s.z += v.z; s.w += v.w;
                    }
                    const int gate = rowl >> 3, j = rowl & 7;
                    const float bb = ((gate == 0) ? br : bz)[wlo1 + J0 + j];
                    float4 g;
                    g.x = sigf(bb + s.x); g.y = sigf(bb + s.y);
                    g.z = sigf(bb + s.z); g.w = sigf(bb + s.w);
                    if (gate == 0) {
                        const float4 h = *(const float4*)(HT1 + (J0 + j)*64 + b4);
                        *(float4*)(sH1 + j*64 + b4) = h;
                        float4 u; u.x=g.x*h.x; u.y=g.y*h.y; u.z=g.z*h.z; u.w=g.w*h.w;
                        *(float4*)(UT1 + (J0 + j)*64 + b4) = u;
                    } else {
                        *(float4*)(sZ1 + j*64 + b4) = g;
                    }
                }
            }
            // s1x partial reduce: 8 rows x 64 b, threads 0..127
            if (L1 && tid < 128) {
                const int rowx = tid >> 4;     // 0..7
                float4 s = make_float4(0.f,0.f,0.f,0.f);
                #pragma unroll
                for (int sp = 0; sp < 8; sp++) {
                    const float4 v = *(const float4*)(sRed + (192 + sp*8 + rowx)*RSTR + b4);
                    s.x += v.x; s.y += v.y; s.z += v.z; s.w += v.w;
                }
                *(float4*)(sS1X + rowx*64 + b4) = s;
            }
        }
        gbar(d);   // u0, u1 visible to all CTAs

        // ---- Phase B ----
        if (L0 && tid < 256)
            gemv8g<16,32>(smem + OFF_WS0, UT0, UT0, sRed, 0, tid);
        if (L1 && tid >= 256)
            gemv8g<16,32>(smem + OFF_WS1 + 512*8, UT1, UT1, sRed, 128, tid - 256);
        __syncthreads();
        {   // fused s reduce: 16 rows x 64 b, float2 per thread
            const int row = tid >> 5;          // 0..15
            const int b2  = (tid & 31) * 2;
            if (row < 8) {
                if (L0) {
                    float sx = 0.f, sy = 0.f;
                    #pragma unroll
                    for (int sp = 0; sp < 16; sp++) {
                        const float2 v = *(const float2*)(sRed + (sp*8 + row)*RSTR + b2);
                        sx += v.x; sy += v.y;
                    }
                    const float2 pre = *(const float2*)(P + (((size_t)2*256 + t0)*512 + J0 + row)*64 + b2);
                    const float ssx = tanhf(pre.x + sx);
                    const float ssy = tanhf(pre.y + sy);
                    const float2 z = *(const float2*)(sZ0 + row*64 + b2);
                    const float2 h = *(const float2*)(sH0 + row*64 + b2);
                    const float hnx = z.x*h.x + (1.f - z.x)*ssx;
                    const float hny = z.y*h.y + (1.f - z.y)*ssy;
                    *(float2*)(HT0n + (J0 + row)*64 + b2) = make_float2(hnx, hny);
                    if (rho == 255) {   // final layer-0 hidden
                        out[(size_t)OUT_SEQ + ((size_t)((d*2+0)*64) + b2    )*512 + J0 + row] = hnx;
                        out[(size_t)OUT_SEQ + ((size_t)((d*2+0)*64) + b2 + 1)*512 + J0 + row] = hny;
                    }
                }
            } else {
                if (L1) {
                    const int rowl = row - 8;
                    float sx = 0.f, sy = 0.f;
                    #pragma unroll
                    for (int sp = 0; sp < 16; sp++) {
                        const float2 v = *(const float2*)(sRed + (128 + sp*8 + rowl)*RSTR + b2);
                        sx += v.x; sy += v.y;
                    }
                    const float2 px = *(const float2*)(sS1X + rowl*64 + b2);
                    const float bb = bs[wlo1 + J0 + rowl];
                    const float ssx = tanhf(bb + px.x + sx);
                    const float ssy = tanhf(bb + px.y + sy);
                    const float2 z = *(const float2*)(sZ1 + rowl*64 + b2);
                    const float2 h = *(const float2*)(sH1 + rowl*64 + b2);
                    const float hnx = z.x*h.x + (1.f - z.x)*ssx;
                    const float hny = z.y*h.y + (1.f - z.y)*ssy;
                    *(float2*)(HT1 + (J0 + rowl)*64 + b2) = make_float2(hnx, hny);
                    out[((size_t)t1*64 + b2    )*1024 + d*512 + J0 + rowl] = hnx;
                    out[((size_t)t1*64 + b2 + 1)*1024 + d*512 + J0 + rowl] = hny;
                    if (rho == 256) {   // final layer-1 hidden
                        out[(size_t)OUT_SEQ + ((size_t)((d*2+1)*64) + b2    )*512 + J0 + rowl] = hnx;
                        out[(size_t)OUT_SEQ + ((size_t)((d*2+1)*64) + b2 + 1)*512 + J0 + rowl] = hny;
                    }
                }
            }
        }
        gbar(d);   // h0n, h1 visible for next round
    }
}

extern "C" void kernel_launch(void* const* d_in, const int* in_sizes, int n_in,
                              void* d_out, int out_size) {
    const int*   tokens = (const int*)  d_in[0];
    const float* emb    = (const float*)d_in[1];
    const float* Wr     = (const float*)d_in[2];
    const float* Wz     = (const float*)d_in[3];
    const float* Ws     = (const float*)d_in[4];
    const float* br     = (const float*)d_in[5];
    const float* bz     = (const float*)d_in[6];
    const float* bs     = (const float*)d_in[7];
    float* out = (float*)d_out;

    cudaFuncSetAttribute(bigru_kernel,
                         cudaFuncAttributeMaxDynamicSharedMemorySize,
                         SMEM_FLOATS * sizeof(float));
    bigru_kernel<<<128, 512, SMEM_FLOATS * sizeof(float)>>>(
        tokens, emb, Wr, Wz, Ws, br, bz, bs, out);
}